// round 1
// baseline (speedup 1.0000x reference)
#include <cuda_runtime.h>
#include <math.h>

#define BB 4
#define SS 2048
#define HH 8
#define DD 64
#define NTOK (BB*SS*HH)   // 65536 tokens

// Scratch (allocation-free rule: __device__ globals)
__device__ float g_qkv[(size_t)NTOK * 192];   // [n][192]  q|k|v
__device__ float g_attn[(size_t)NTOK * 64];   // [n][64]   attention out, token layout

// ---------------------------------------------------------------------------
// Kernel 1: LN1 + QKV projection.  64 tokens/block, 256 threads.
// smem: Wp[64][192] + h[64][65]
// ---------------------------------------------------------------------------
__global__ __launch_bounds__(256)
void k1_ln_qkv(const float* __restrict__ x,
               const float* __restrict__ g1, const float* __restrict__ b1v,
               const float* __restrict__ Wp, const float* __restrict__ bp)
{
    extern __shared__ float sm1[];
    float* sW = sm1;              // 64*192
    float* sh = sm1 + 64 * 192;   // 64*65

    const int tid = threadIdx.x;
    const int t0  = blockIdx.x * 64;

    for (int i = tid; i < 64 * 192; i += 256) sW[i] = Wp[i];

    // LayerNorm: 4 threads per token, 16 elems each
    {
        const int tt = tid >> 2, sub = tid & 3;
        const size_t base = ((size_t)(t0 + tt)) * 64 + sub * 16;
        float v[16];
        const float4* xp = (const float4*)(x + base);
        #pragma unroll
        for (int q = 0; q < 4; q++) {
            float4 f = xp[q];
            v[4*q+0] = f.x; v[4*q+1] = f.y; v[4*q+2] = f.z; v[4*q+3] = f.w;
        }
        float s = 0.f;
        #pragma unroll
        for (int q = 0; q < 16; q++) s += v[q];
        s += __shfl_xor_sync(0xffffffffu, s, 1);
        s += __shfl_xor_sync(0xffffffffu, s, 2);
        const float mean = s * (1.f / 64.f);
        float vs = 0.f;
        #pragma unroll
        for (int q = 0; q < 16; q++) { float d = v[q] - mean; vs += d * d; }
        vs += __shfl_xor_sync(0xffffffffu, vs, 1);
        vs += __shfl_xor_sync(0xffffffffu, vs, 2);
        const float rs = rsqrtf(vs * (1.f / 64.f) + 1e-5f);
        #pragma unroll
        for (int q = 0; q < 16; q++) {
            int d = sub * 16 + q;
            sh[tt * 65 + d] = (v[q] - mean) * rs * g1[d] + b1v[d];
        }
    }
    __syncthreads();

    // GEMM 64x192x64: thread (tg,cg) owns 4 tokens x 12 cols (cols cg+16m)
    const int tg = tid >> 4, cg = tid & 15;
    float acc[4][12];
    #pragma unroll
    for (int i = 0; i < 4; i++)
        #pragma unroll
        for (int m = 0; m < 12; m++) acc[i][m] = 0.f;

    for (int d = 0; d < 64; d++) {
        float hv[4];
        #pragma unroll
        for (int i = 0; i < 4; i++) hv[i] = sh[(tg * 4 + i) * 65 + d];
        #pragma unroll
        for (int m = 0; m < 12; m++) {
            float w = sW[d * 192 + cg + 16 * m];
            #pragma unroll
            for (int i = 0; i < 4; i++) acc[i][m] += hv[i] * w;
        }
    }
    #pragma unroll
    for (int i = 0; i < 4; i++) {
        const size_t n = (size_t)(t0 + tg * 4 + i);
        #pragma unroll
        for (int m = 0; m < 12; m++) {
            int col = cg + 16 * m;
            g_qkv[n * 192 + col] = acc[i][m] + bp[col];
        }
    }
}

// ---------------------------------------------------------------------------
// Kernel 2: flash attention.  grid (S/64, B*H), 256 threads.
// smem: Qs/Ks/Vt/Ps each [64][68] floats
// ---------------------------------------------------------------------------
__global__ __launch_bounds__(256)
void k2_attn()
{
    extern __shared__ float sm2[];
    float* Qs = sm2;
    float* Ks = sm2 + 64 * 68;
    float* Vt = sm2 + 2 * 64 * 68;   // transposed: Vt[d][row]
    float* Ps = sm2 + 3 * 64 * 68;

    const int tid = threadIdx.x;
    const int tx = tid & 15, ty = tid >> 4;
    const int qb = blockIdx.x, bh = blockIdx.y;
    const int b = bh >> 3, h = bh & 7;
    const int q0 = qb * 64;

    // load Q tile
    for (int it = tid; it < 1024; it += 256) {
        const int row = it >> 4, f4 = it & 15;
        const size_t n = ((size_t)(b * SS + q0 + row)) * HH + h;
        float4 v = *(const float4*)(g_qkv + n * 192 + f4 * 4);
        *(float4*)(Qs + row * 68 + f4 * 4) = v;
    }

    float m[4], l[4], O[4][4];
    #pragma unroll
    for (int i = 0; i < 4; i++) {
        m[i] = -INFINITY; l[i] = 0.f;
        #pragma unroll
        for (int j = 0; j < 4; j++) O[i][j] = 0.f;
    }

    for (int kt = 0; kt < SS / 64; kt++) {
        __syncthreads();   // previous PV done before overwriting Ks/Vt
        const int k0 = kt * 64;
        for (int it = tid; it < 1024; it += 256) {
            const int row = it >> 4, f4 = it & 15;
            const size_t n = ((size_t)(b * SS + k0 + row)) * HH + h;
            float4 kv = *(const float4*)(g_qkv + n * 192 + 64 + f4 * 4);
            *(float4*)(Ks + row * 68 + f4 * 4) = kv;
            float4 vv = *(const float4*)(g_qkv + n * 192 + 128 + f4 * 4);
            const int d0 = f4 * 4;
            Vt[(d0 + 0) * 68 + row] = vv.x;
            Vt[(d0 + 1) * 68 + row] = vv.y;
            Vt[(d0 + 2) * 68 + row] = vv.z;
            Vt[(d0 + 3) * 68 + row] = vv.w;
        }
        __syncthreads();

        // S = Q K^T (4x4 tile per thread)
        float s[4][4];
        #pragma unroll
        for (int i = 0; i < 4; i++)
            #pragma unroll
            for (int j = 0; j < 4; j++) s[i][j] = 0.f;

        #pragma unroll 4
        for (int d = 0; d < 64; d += 4) {
            float4 qv[4], kv[4];
            #pragma unroll
            for (int i = 0; i < 4; i++) qv[i] = *(float4*)(Qs + (ty * 4 + i) * 68 + d);
            #pragma unroll
            for (int j = 0; j < 4; j++) kv[j] = *(float4*)(Ks + (tx * 4 + j) * 68 + d);
            #pragma unroll
            for (int i = 0; i < 4; i++)
                #pragma unroll
                for (int j = 0; j < 4; j++)
                    s[i][j] += qv[i].x * kv[j].x + qv[i].y * kv[j].y
                             + qv[i].z * kv[j].z + qv[i].w * kv[j].w;
        }

        // online softmax
        #pragma unroll
        for (int i = 0; i < 4; i++) {
            float r = s[i][0];
            #pragma unroll
            for (int j = 1; j < 4; j++) r = fmaxf(r, s[i][j]);
            r = fmaxf(r, __shfl_xor_sync(0xffffffffu, r, 1));
            r = fmaxf(r, __shfl_xor_sync(0xffffffffu, r, 2));
            r = fmaxf(r, __shfl_xor_sync(0xffffffffu, r, 4));
            r = fmaxf(r, __shfl_xor_sync(0xffffffffu, r, 8));
            const float mn = fmaxf(m[i], r);
            const float al = __expf(m[i] - mn);
            m[i] = mn;
            float ssum = 0.f;
            #pragma unroll
            for (int j = 0; j < 4; j++) {
                float p = __expf(s[i][j] - mn);
                ssum += p;
                Ps[(ty * 4 + i) * 68 + tx * 4 + j] = p;
            }
            ssum += __shfl_xor_sync(0xffffffffu, ssum, 1);
            ssum += __shfl_xor_sync(0xffffffffu, ssum, 2);
            ssum += __shfl_xor_sync(0xffffffffu, ssum, 4);
            ssum += __shfl_xor_sync(0xffffffffu, ssum, 8);
            l[i] = l[i] * al + ssum;
            #pragma unroll
            for (int j = 0; j < 4; j++) O[i][j] *= al;
        }
        __syncthreads();

        // O += P V   (Vt is [d_out][k], same dot4 structure as QK)
        #pragma unroll 4
        for (int k = 0; k < 64; k += 4) {
            float4 pv[4], vv[4];
            #pragma unroll
            for (int i = 0; i < 4; i++) pv[i] = *(float4*)(Ps + (ty * 4 + i) * 68 + k);
            #pragma unroll
            for (int j = 0; j < 4; j++) vv[j] = *(float4*)(Vt + (tx * 4 + j) * 68 + k);
            #pragma unroll
            for (int i = 0; i < 4; i++)
                #pragma unroll
                for (int j = 0; j < 4; j++)
                    O[i][j] += pv[i].x * vv[j].x + pv[i].y * vv[j].y
                             + pv[i].z * vv[j].z + pv[i].w * vv[j].w;
        }
    }

    // epilogue
    #pragma unroll
    for (int i = 0; i < 4; i++) {
        const float inv = 1.f / l[i];
        const size_t n = ((size_t)(b * SS + q0 + ty * 4 + i)) * HH + h;
        #pragma unroll
        for (int j = 0; j < 4; j++)
            g_attn[n * 64 + tx * 4 + j] = O[i][j] * inv;
    }
}

// ---------------------------------------------------------------------------
// Kernel 3: LN2 + MLP (gelu exact) + residual.  32 tokens/block, 256 threads.
// smem: W1[64][256] + W2[256][64] + a[32][65] + h1[32][256]
// ---------------------------------------------------------------------------
__global__ __launch_bounds__(256)
void k3_ln_mlp(const float* __restrict__ x,
               const float* __restrict__ g2, const float* __restrict__ b2v,
               const float* __restrict__ W1, const float* __restrict__ b1m,
               const float* __restrict__ W2, const float* __restrict__ b2m,
               float* __restrict__ out)
{
    extern __shared__ float sm3[];
    float* sW1 = sm3;                   // 64*256
    float* sW2 = sW1 + 64 * 256;        // 256*64
    float* sa  = sW2 + 256 * 64;        // 32*65
    float* sh1 = sa + 32 * 65;          // 32*256

    const int tid = threadIdx.x;
    const int t0 = blockIdx.x * 32;

    for (int i = tid; i < 64 * 256; i += 256) sW1[i] = W1[i];
    for (int i = tid; i < 256 * 64; i += 256) sW2[i] = W2[i];

    // LN2 on attention output: 8 threads per token, 8 elems each
    {
        const int tt = tid >> 3, sub = tid & 7;
        const size_t base = ((size_t)(t0 + tt)) * 64 + sub * 8;
        float v[8];
        const float4* ap = (const float4*)(g_attn + base);
        float4 f0 = ap[0], f1 = ap[1];
        v[0]=f0.x; v[1]=f0.y; v[2]=f0.z; v[3]=f0.w;
        v[4]=f1.x; v[5]=f1.y; v[6]=f1.z; v[7]=f1.w;
        float s = 0.f;
        #pragma unroll
        for (int q = 0; q < 8; q++) s += v[q];
        s += __shfl_xor_sync(0xffffffffu, s, 1);
        s += __shfl_xor_sync(0xffffffffu, s, 2);
        s += __shfl_xor_sync(0xffffffffu, s, 4);
        const float mean = s * (1.f / 64.f);
        float vs = 0.f;
        #pragma unroll
        for (int q = 0; q < 8; q++) { float d = v[q] - mean; vs += d * d; }
        vs += __shfl_xor_sync(0xffffffffu, vs, 1);
        vs += __shfl_xor_sync(0xffffffffu, vs, 2);
        vs += __shfl_xor_sync(0xffffffffu, vs, 4);
        const float rs = rsqrtf(vs * (1.f / 64.f) + 1e-5f);
        #pragma unroll
        for (int q = 0; q < 8; q++) {
            int d = sub * 8 + q;
            sa[tt * 65 + d] = (v[q] - mean) * rs * g2[d] + b2v[d];
        }
    }
    __syncthreads();

    // GEMM1: [32,64] @ [64,256] + gelu -> sh1 ; thread owns 4 tok x 8 cols (cg+32m)
    const int tg = tid >> 5, cg = tid & 31;
    {
        float a1[4][8];
        #pragma unroll
        for (int i = 0; i < 4; i++)
            #pragma unroll
            for (int mcol = 0; mcol < 8; mcol++) a1[i][mcol] = 0.f;
        for (int d = 0; d < 64; d++) {
            float hv[4];
            #pragma unroll
            for (int i = 0; i < 4; i++) hv[i] = sa[(tg * 4 + i) * 65 + d];
            #pragma unroll
            for (int mcol = 0; mcol < 8; mcol++) {
                float w = sW1[d * 256 + cg + 32 * mcol];
                #pragma unroll
                for (int i = 0; i < 4; i++) a1[i][mcol] += hv[i] * w;
            }
        }
        #pragma unroll
        for (int i = 0; i < 4; i++)
            #pragma unroll
            for (int mcol = 0; mcol < 8; mcol++) {
                int col = cg + 32 * mcol;
                float z = a1[i][mcol] + b1m[col];
                float ge = 0.5f * z * (1.f + erff(z * 0.70710678118654752f));
                sh1[(tg * 4 + i) * 256 + col] = ge;
            }
    }
    __syncthreads();

    // GEMM2: [32,256] @ [256,64] + b2 + residual ; thread owns 4 tok x 2 cols
    {
        float a2[4][2];
        #pragma unroll
        for (int i = 0; i < 4; i++) { a2[i][0] = 0.f; a2[i][1] = 0.f; }
        for (int k = 0; k < 256; k++) {
            float w0 = sW2[k * 64 + cg];
            float w1 = sW2[k * 64 + cg + 32];
            #pragma unroll
            for (int i = 0; i < 4; i++) {
                float hv = sh1[(tg * 4 + i) * 256 + k];
                a2[i][0] += hv * w0;
                a2[i][1] += hv * w1;
            }
        }
        #pragma unroll
        for (int i = 0; i < 4; i++) {
            const size_t n = (size_t)(t0 + tg * 4 + i);
            #pragma unroll
            for (int jj = 0; jj < 2; jj++) {
                int col = cg + 32 * jj;
                out[n * 64 + col] = a2[i][jj] + b2m[col] + x[n * 64 + col];
            }
        }
    }
}

// ---------------------------------------------------------------------------
extern "C" void kernel_launch(void* const* d_in, const int* in_sizes, int n_in,
                              void* d_out, int out_size)
{
    const float* x    = (const float*)d_in[0];
    const float* ln1g = (const float*)d_in[1];
    const float* ln1b = (const float*)d_in[2];
    const float* Wp   = (const float*)d_in[3];
    const float* bp   = (const float*)d_in[4];
    const float* ln2g = (const float*)d_in[5];
    const float* ln2b = (const float*)d_in[6];
    const float* W1   = (const float*)d_in[7];
    const float* b1   = (const float*)d_in[8];
    const float* W2   = (const float*)d_in[9];
    const float* b2   = (const float*)d_in[10];
    float* out = (float*)d_out;

    const int smem1 = (64 * 192 + 64 * 65) * 4;                       // 65,792
    const int smem2 = 4 * 64 * 68 * 4;                                // 69,632
    const int smem3 = (64 * 256 + 256 * 64 + 32 * 65 + 32 * 256) * 4; // 172,160

    cudaFuncSetAttribute(k1_ln_qkv, cudaFuncAttributeMaxDynamicSharedMemorySize, smem1);
    cudaFuncSetAttribute(k2_attn,   cudaFuncAttributeMaxDynamicSharedMemorySize, smem2);
    cudaFuncSetAttribute(k3_ln_mlp, cudaFuncAttributeMaxDynamicSharedMemorySize, smem3);

    k1_ln_qkv<<<NTOK / 64, 256, smem1>>>(x, ln1g, ln1b, Wp, bp);
    k2_attn<<<dim3(SS / 64, BB * HH), 256, smem2>>>();
    k3_ln_mlp<<<NTOK / 32, 256, smem3>>>(x, ln2g, ln2b, W1, b1, W2, b2, out);
}

// round 3
// speedup vs baseline: 4.0784x; 4.0784x over previous
#include <cuda_runtime.h>
#include <cuda_bf16.h>
#include <math.h>
#include <stdint.h>

#define BB 4
#define SS 2048
#define HH 8
#define DD 64
#define NTOK (BB*SS*HH)   // 65536 tokens

// Scratch (allocation-free rule: __device__ globals)
__device__ float g_qkv[(size_t)NTOK * 192];   // [n][192]  q|k|v
__device__ float g_attn[(size_t)NTOK * 64];   // [n][64]   attention out, token layout

// ===========================================================================
// Kernel 1: LN1 + QKV projection.  64 tokens/block, 256 threads. (unchanged)
// ===========================================================================
__global__ __launch_bounds__(256)
void k1_ln_qkv(const float* __restrict__ x,
               const float* __restrict__ g1, const float* __restrict__ b1v,
               const float* __restrict__ Wp, const float* __restrict__ bp)
{
    extern __shared__ float sm1[];
    float* sW = sm1;              // 64*192
    float* sh = sm1 + 64 * 192;   // 64*65

    const int tid = threadIdx.x;
    const int t0  = blockIdx.x * 64;

    for (int i = tid; i < 64 * 192; i += 256) sW[i] = Wp[i];

    {
        const int tt = tid >> 2, sub = tid & 3;
        const size_t base = ((size_t)(t0 + tt)) * 64 + sub * 16;
        float v[16];
        const float4* xp = (const float4*)(x + base);
        #pragma unroll
        for (int q = 0; q < 4; q++) {
            float4 f = xp[q];
            v[4*q+0] = f.x; v[4*q+1] = f.y; v[4*q+2] = f.z; v[4*q+3] = f.w;
        }
        float s = 0.f;
        #pragma unroll
        for (int q = 0; q < 16; q++) s += v[q];
        s += __shfl_xor_sync(0xffffffffu, s, 1);
        s += __shfl_xor_sync(0xffffffffu, s, 2);
        const float mean = s * (1.f / 64.f);
        float vs = 0.f;
        #pragma unroll
        for (int q = 0; q < 16; q++) { float d = v[q] - mean; vs += d * d; }
        vs += __shfl_xor_sync(0xffffffffu, vs, 1);
        vs += __shfl_xor_sync(0xffffffffu, vs, 2);
        const float rs = rsqrtf(vs * (1.f / 64.f) + 1e-5f);
        #pragma unroll
        for (int q = 0; q < 16; q++) {
            int d = sub * 16 + q;
            sh[tt * 65 + d] = (v[q] - mean) * rs * g1[d] + b1v[d];
        }
    }
    __syncthreads();

    const int tg = tid >> 4, cg = tid & 15;
    float acc[4][12];
    #pragma unroll
    for (int i = 0; i < 4; i++)
        #pragma unroll
        for (int m = 0; m < 12; m++) acc[i][m] = 0.f;

    for (int d = 0; d < 64; d++) {
        float hv[4];
        #pragma unroll
        for (int i = 0; i < 4; i++) hv[i] = sh[(tg * 4 + i) * 65 + d];
        #pragma unroll
        for (int m = 0; m < 12; m++) {
            float w = sW[d * 192 + cg + 16 * m];
            #pragma unroll
            for (int i = 0; i < 4; i++) acc[i][m] += hv[i] * w;
        }
    }
    #pragma unroll
    for (int i = 0; i < 4; i++) {
        const size_t n = (size_t)(t0 + tg * 4 + i);
        #pragma unroll
        for (int m = 0; m < 12; m++) {
            int col = cg + 16 * m;
            g_qkv[n * 192 + col] = acc[i][m] + bp[col];
        }
    }
}

// ===========================================================================
// Helpers for mma.sync path
// ===========================================================================
__device__ __forceinline__ uint32_t smem_u32(const void* p) {
    uint32_t a;
    asm("{ .reg .u64 t; cvta.to.shared.u64 t, %1; cvt.u32.u64 %0, t; }"
        : "=r"(a) : "l"(p));
    return a;
}

__device__ __forceinline__ void split2(float a, float b, uint32_t& hi, uint32_t& lo) {
    __nv_bfloat16 ha = __float2bfloat16(a), hb = __float2bfloat16(b);
    float ra = a - __bfloat162float(ha), rb = b - __bfloat162float(hb);
    __nv_bfloat16 la = __float2bfloat16(ra), lb = __float2bfloat16(rb);
    hi = (uint32_t)__bfloat16_as_ushort(ha) | ((uint32_t)__bfloat16_as_ushort(hb) << 16);
    lo = (uint32_t)__bfloat16_as_ushort(la) | ((uint32_t)__bfloat16_as_ushort(lb) << 16);
}

#define LDSM_X4(r0,r1,r2,r3, addr) \
    asm volatile("ldmatrix.sync.aligned.m8n8.x4.shared.b16 {%0,%1,%2,%3}, [%4];" \
        : "=r"(r0), "=r"(r1), "=r"(r2), "=r"(r3) : "r"(addr))
#define LDSM_X4_T(r0,r1,r2,r3, addr) \
    asm volatile("ldmatrix.sync.aligned.m8n8.x4.trans.shared.b16 {%0,%1,%2,%3}, [%4];" \
        : "=r"(r0), "=r"(r1), "=r"(r2), "=r"(r3) : "r"(addr))

__device__ __forceinline__ void mma16816(float* d, uint32_t a0, uint32_t a1,
                                         uint32_t a2, uint32_t a3,
                                         uint32_t b0, uint32_t b1) {
    asm volatile(
        "mma.sync.aligned.m16n8k16.row.col.f32.bf16.bf16.f32 "
        "{%0,%1,%2,%3}, {%4,%5,%6,%7}, {%8,%9}, {%0,%1,%2,%3};"
        : "+f"(d[0]), "+f"(d[1]), "+f"(d[2]), "+f"(d[3])
        : "r"(a0), "r"(a1), "r"(a2), "r"(a3), "r"(b0), "r"(b1));
}

// smem byte layout for k2
#define QPITCH 400          // 200 bf16 elems/row (Qh|Ql|Qh + pad)
#define KPITCH 400          // 200 bf16 elems/row (Kh|Kh|Kl + pad)
#define VPITCH 272          // 136 bf16 elems/row (Vh|Vl + pad)
#define SM_Q 0
#define SM_K (128 * QPITCH)                 // 51200
#define SM_V (SM_K + 64 * KPITCH)           // 76800
#define SM2_TOTAL (SM_V + 64 * VPITCH)      // 94208

// ===========================================================================
// Kernel 2: flash attention via mma.sync bf16 hi/lo split, no-max softmax.
// 256 threads (8 warps x 16 q-rows = 128 q-rows/block).  grid (S/128, B*H).
// ===========================================================================
__global__ __launch_bounds__(256)
void k2_attn_mma()
{
    extern __shared__ char smc[];
    const uint32_t sbQ = smem_u32(smc) + SM_Q;
    const uint32_t sbK = smem_u32(smc) + SM_K;
    const uint32_t sbV = smem_u32(smc) + SM_V;

    const int tid  = threadIdx.x;
    const int wid  = tid >> 5;
    const int lane = tid & 31;
    const int b = blockIdx.y >> 3, h = blockIdx.y & 7;
    const int q0 = blockIdx.x * 128;
    const int m0 = wid * 16;

    const int g  = lane >> 3;     // ldmatrix lane group
    const int lr = lane & 7;

    // per-lane ldmatrix base addresses
    const uint32_t aQ = sbQ + (uint32_t)(m0 + (g & 1) * 8 + lr) * QPITCH + (g >> 1) * 16;
    const uint32_t aK = sbK + (uint32_t)((g >> 1) * 8 + lr) * KPITCH + (g & 1) * 16;
    const uint32_t aV = sbV + (uint32_t)((g & 1) * 8 + lr) * VPITCH + (g >> 1) * 16;

    // ---- load Q tile [128][64] -> Q_ext [Qh | Ql | Qh] ----
    for (int it = tid; it < 2048; it += 256) {
        const int row = it >> 4, c4 = it & 15;
        const size_t n = ((size_t)(b * SS + q0 + row)) * HH + h;
        float4 f = *(const float4*)(g_qkv + n * 192 + c4 * 4);
        uint32_t h01, l01, h23, l23;
        split2(f.x, f.y, h01, l01);
        split2(f.z, f.w, h23, l23);
        char* base = smc + SM_Q + row * QPITCH + c4 * 8;
        *(uint2*)(base)       = make_uint2(h01, h23);   // Qh  cols 0..63
        *(uint2*)(base + 128) = make_uint2(l01, l23);   // Ql  cols 64..127
        *(uint2*)(base + 256) = make_uint2(h01, h23);   // Qh dup cols 128..191
    }

    float o[8][4];
    #pragma unroll
    for (int j = 0; j < 8; j++)
        #pragma unroll
        for (int e = 0; e < 4; e++) o[j][e] = 0.f;
    float lsum0 = 0.f, lsum1 = 0.f;

    for (int kt = 0; kt < SS / 64; kt++) {
        __syncthreads();   // prev iter done reading K/V
        const int k0 = kt * 64;
        // ---- load K -> [Kh|Kh|Kl],  V -> [Vh|Vl] ----
        for (int it = tid; it < 1024; it += 256) {
            const int row = it >> 4, c4 = it & 15;
            const float* src = g_qkv + (((size_t)(b * SS + k0 + row)) * HH + h) * 192;
            float4 kf = *(const float4*)(src + 64 + c4 * 4);
            uint32_t h01, l01, h23, l23;
            split2(kf.x, kf.y, h01, l01);
            split2(kf.z, kf.w, h23, l23);
            char* kb = smc + SM_K + row * KPITCH + c4 * 8;
            *(uint2*)(kb)       = make_uint2(h01, h23);   // Kh
            *(uint2*)(kb + 128) = make_uint2(h01, h23);   // Kh dup
            *(uint2*)(kb + 256) = make_uint2(l01, l23);   // Kl
            float4 vf = *(const float4*)(src + 128 + c4 * 4);
            split2(vf.x, vf.y, h01, l01);
            split2(vf.z, vf.w, h23, l23);
            char* vb = smc + SM_V + row * VPITCH + c4 * 8;
            *(uint2*)(vb)       = make_uint2(h01, h23);   // Vh cols 0..63
            *(uint2*)(vb + 128) = make_uint2(l01, l23);   // Vl cols 64..127
        }
        __syncthreads();

        // ---- S = Qh*Kh + Ql*Kh + Qh*Kl  (K-ext loop, 12 k-steps) ----
        float s[8][4];
        #pragma unroll
        for (int j = 0; j < 8; j++)
            #pragma unroll
            for (int e = 0; e < 4; e++) s[j][e] = 0.f;

        #pragma unroll
        for (int ks = 0; ks < 12; ks++) {
            uint32_t qa0, qa1, qa2, qa3;
            LDSM_X4(qa0, qa1, qa2, qa3, aQ + ks * 32);
            #pragma unroll
            for (int j = 0; j < 4; j++) {
                uint32_t kb0, kb1, kb2, kb3;
                LDSM_X4(kb0, kb1, kb2, kb3, aK + ks * 32 + j * (16 * KPITCH));
                mma16816(s[2*j],     qa0, qa1, qa2, qa3, kb0, kb1);
                mma16816(s[2*j + 1], qa0, qa1, qa2, qa3, kb2, kb3);
            }
        }

        // ---- softmax (no max subtraction) + build P fragments in regs ----
        uint32_t ph[4][4], pl[4][4];
        #pragma unroll
        for (int j = 0; j < 8; j++) {
            float p0 = __expf(s[j][0]);
            float p1 = __expf(s[j][1]);
            float p2 = __expf(s[j][2]);
            float p3 = __expf(s[j][3]);
            lsum0 += p0 + p1;
            lsum1 += p2 + p3;
            uint32_t h01, l01, h23, l23;
            split2(p0, p1, h01, l01);
            split2(p2, p3, h23, l23);
            const int ktf = j >> 1, q = (j & 1) * 2;
            ph[ktf][q + 0] = h01;  pl[ktf][q + 0] = l01;
            ph[ktf][q + 1] = h23;  pl[ktf][q + 1] = l23;
        }

        // ---- O += Ph*Vh + Pl*Vh + Ph*Vl ----
        #pragma unroll
        for (int j = 0; j < 4; j++) {
            #pragma unroll
            for (int kk = 0; kk < 4; kk++) {
                uint32_t vh0, vh1, vh2, vh3, vl0, vl1, vl2, vl3;
                const uint32_t av = aV + kk * (16 * VPITCH) + j * 32;
                LDSM_X4_T(vh0, vh1, vh2, vh3, av);
                LDSM_X4_T(vl0, vl1, vl2, vl3, av + 128);
                mma16816(o[2*j],     ph[kk][0], ph[kk][1], ph[kk][2], ph[kk][3], vh0, vh1);
                mma16816(o[2*j + 1], ph[kk][0], ph[kk][1], ph[kk][2], ph[kk][3], vh2, vh3);
                mma16816(o[2*j],     pl[kk][0], pl[kk][1], pl[kk][2], pl[kk][3], vh0, vh1);
                mma16816(o[2*j + 1], pl[kk][0], pl[kk][1], pl[kk][2], pl[kk][3], vh2, vh3);
                mma16816(o[2*j],     ph[kk][0], ph[kk][1], ph[kk][2], ph[kk][3], vl0, vl1);
                mma16816(o[2*j + 1], ph[kk][0], ph[kk][1], ph[kk][2], ph[kk][3], vl2, vl3);
            }
        }
    }

    // ---- epilogue: reduce row sums across quad, normalize, store ----
    lsum0 += __shfl_xor_sync(0xffffffffu, lsum0, 1);
    lsum0 += __shfl_xor_sync(0xffffffffu, lsum0, 2);
    lsum1 += __shfl_xor_sync(0xffffffffu, lsum1, 1);
    lsum1 += __shfl_xor_sync(0xffffffffu, lsum1, 2);
    const float inv0 = 1.f / lsum0, inv1 = 1.f / lsum1;

    const int r0 = q0 + m0 + (lane >> 2);
    const int c0 = (lane & 3) * 2;
    const size_t n0 = ((size_t)(b * SS + r0)) * HH + h;
    const size_t n1 = ((size_t)(b * SS + r0 + 8)) * HH + h;
    #pragma unroll
    for (int j = 0; j < 8; j++) {
        float2 v0 = make_float2(o[j][0] * inv0, o[j][1] * inv0);
        float2 v1 = make_float2(o[j][2] * inv1, o[j][3] * inv1);
        *(float2*)(g_attn + n0 * 64 + 8 * j + c0) = v0;
        *(float2*)(g_attn + n1 * 64 + 8 * j + c0) = v1;
    }
}

// ===========================================================================
// Kernel 3: LN2 + MLP (gelu exact) + residual. (unchanged)
// ===========================================================================
__global__ __launch_bounds__(256)
void k3_ln_mlp(const float* __restrict__ x,
               const float* __restrict__ g2, const float* __restrict__ b2v,
               const float* __restrict__ W1, const float* __restrict__ b1m,
               const float* __restrict__ W2, const float* __restrict__ b2m,
               float* __restrict__ out)
{
    extern __shared__ float sm3[];
    float* sW1 = sm3;                   // 64*256
    float* sW2 = sW1 + 64 * 256;        // 256*64
    float* sa  = sW2 + 256 * 64;        // 32*65
    float* sh1 = sa + 32 * 65;          // 32*256

    const int tid = threadIdx.x;
    const int t0 = blockIdx.x * 32;

    for (int i = tid; i < 64 * 256; i += 256) sW1[i] = W1[i];
    for (int i = tid; i < 256 * 64; i += 256) sW2[i] = W2[i];

    {
        const int tt = tid >> 3, sub = tid & 7;
        const size_t base = ((size_t)(t0 + tt)) * 64 + sub * 8;
        float v[8];
        const float4* ap = (const float4*)(g_attn + base);
        float4 f0 = ap[0], f1 = ap[1];
        v[0]=f0.x; v[1]=f0.y; v[2]=f0.z; v[3]=f0.w;
        v[4]=f1.x; v[5]=f1.y; v[6]=f1.z; v[7]=f1.w;
        float s = 0.f;
        #pragma unroll
        for (int q = 0; q < 8; q++) s += v[q];
        s += __shfl_xor_sync(0xffffffffu, s, 1);
        s += __shfl_xor_sync(0xffffffffu, s, 2);
        s += __shfl_xor_sync(0xffffffffu, s, 4);
        const float mean = s * (1.f / 64.f);
        float vs = 0.f;
        #pragma unroll
        for (int q = 0; q < 8; q++) { float d = v[q] - mean; vs += d * d; }
        vs += __shfl_xor_sync(0xffffffffu, vs, 1);
        vs += __shfl_xor_sync(0xffffffffu, vs, 2);
        vs += __shfl_xor_sync(0xffffffffu, vs, 4);
        const float rs = rsqrtf(vs * (1.f / 64.f) + 1e-5f);
        #pragma unroll
        for (int q = 0; q < 8; q++) {
            int d = sub * 8 + q;
            sa[tt * 65 + d] = (v[q] - mean) * rs * g2[d] + b2v[d];
        }
    }
    __syncthreads();

    const int tg = tid >> 5, cg = tid & 31;
    {
        float a1[4][8];
        #pragma unroll
        for (int i = 0; i < 4; i++)
            #pragma unroll
            for (int mcol = 0; mcol < 8; mcol++) a1[i][mcol] = 0.f;
        for (int d = 0; d < 64; d++) {
            float hv[4];
            #pragma unroll
            for (int i = 0; i < 4; i++) hv[i] = sa[(tg * 4 + i) * 65 + d];
            #pragma unroll
            for (int mcol = 0; mcol < 8; mcol++) {
                float w = sW1[d * 256 + cg + 32 * mcol];
                #pragma unroll
                for (int i = 0; i < 4; i++) a1[i][mcol] += hv[i] * w;
            }
        }
        #pragma unroll
        for (int i = 0; i < 4; i++)
            #pragma unroll
            for (int mcol = 0; mcol < 8; mcol++) {
                int col = cg + 32 * mcol;
                float z = a1[i][mcol] + b1m[col];
                float ge = 0.5f * z * (1.f + erff(z * 0.70710678118654752f));
                sh1[(tg * 4 + i) * 256 + col] = ge;
            }
    }
    __syncthreads();

    {
        float a2[4][2];
        #pragma unroll
        for (int i = 0; i < 4; i++) { a2[i][0] = 0.f; a2[i][1] = 0.f; }
        for (int k = 0; k < 256; k++) {
            float w0 = sW2[k * 64 + cg];
            float w1 = sW2[k * 64 + cg + 32];
            #pragma unroll
            for (int i = 0; i < 4; i++) {
                float hv = sh1[(tg * 4 + i) * 256 + k];
                a2[i][0] += hv * w0;
                a2[i][1] += hv * w1;
            }
        }
        #pragma unroll
        for (int i = 0; i < 4; i++) {
            const size_t n = (size_t)(t0 + tg * 4 + i);
            #pragma unroll
            for (int jj = 0; jj < 2; jj++) {
                int col = cg + 32 * jj;
                out[n * 64 + col] = a2[i][jj] + b2m[col] + x[n * 64 + col];
            }
        }
    }
}

// ===========================================================================
extern "C" void kernel_launch(void* const* d_in, const int* in_sizes, int n_in,
                              void* d_out, int out_size)
{
    const float* x    = (const float*)d_in[0];
    const float* ln1g = (const float*)d_in[1];
    const float* ln1b = (const float*)d_in[2];
    const float* Wp   = (const float*)d_in[3];
    const float* bp   = (const float*)d_in[4];
    const float* ln2g = (const float*)d_in[5];
    const float* ln2b = (const float*)d_in[6];
    const float* W1   = (const float*)d_in[7];
    const float* b1   = (const float*)d_in[8];
    const float* W2   = (const float*)d_in[9];
    const float* b2   = (const float*)d_in[10];
    float* out = (float*)d_out;

    const int smem1 = (64 * 192 + 64 * 65) * 4;
    const int smem2 = SM2_TOTAL;
    const int smem3 = (64 * 256 + 256 * 64 + 32 * 65 + 32 * 256) * 4;

    cudaFuncSetAttribute(k1_ln_qkv,   cudaFuncAttributeMaxDynamicSharedMemorySize, smem1);
    cudaFuncSetAttribute(k2_attn_mma, cudaFuncAttributeMaxDynamicSharedMemorySize, smem2);
    cudaFuncSetAttribute(k3_ln_mlp,   cudaFuncAttributeMaxDynamicSharedMemorySize, smem3);

    k1_ln_qkv<<<NTOK / 64, 256, smem1>>>(x, ln1g, ln1b, Wp, bp);
    k2_attn_mma<<<dim3(SS / 128, BB * HH), 256, smem2>>>();
    k3_ln_mlp<<<NTOK / 32, 256, smem3>>>(x, ln2g, ln2b, W1, b1, W2, b2, out);
}

// round 4
// speedup vs baseline: 5.4505x; 1.3364x over previous
#include <cuda_runtime.h>
#include <cuda_bf16.h>
#include <cuda_fp16.h>
#include <math.h>
#include <stdint.h>

#define BB 4
#define SS 2048
#define HH 8
#define DD 64
#define NTOK (BB*SS*HH)   // 65536 tokens

// Scratch (allocation-free rule: __device__ globals)
__device__ __nv_bfloat16 g_qkh[(size_t)NTOK * 128];  // [n][128] q|k hi parts
__device__ __nv_bfloat16 g_qkl[(size_t)NTOK * 128];  // [n][128] q|k lo parts
__device__ __half        g_v  [(size_t)NTOK * 64];   // [n][64]  v fp16
__device__ float         g_attn[(size_t)NTOK * 64];  // [n][64]  attention out

// ===========================================================================
// Kernel 1: LN1 + QKV projection.  64 tokens/block, 256 threads.
// Outputs pre-split bf16 hi/lo (q,k) and fp16 (v).
// ===========================================================================
__global__ __launch_bounds__(256)
void k1_ln_qkv(const float* __restrict__ x,
               const float* __restrict__ g1, const float* __restrict__ b1v,
               const float* __restrict__ Wp, const float* __restrict__ bp)
{
    extern __shared__ float sm1[];
    float* sW = sm1;              // 64*192
    float* sh = sm1 + 64 * 192;   // 64*65

    const int tid = threadIdx.x;
    const int t0  = blockIdx.x * 64;

    for (int i = tid; i < 64 * 192; i += 256) sW[i] = Wp[i];

    {
        const int tt = tid >> 2, sub = tid & 3;
        const size_t base = ((size_t)(t0 + tt)) * 64 + sub * 16;
        float v[16];
        const float4* xp = (const float4*)(x + base);
        #pragma unroll
        for (int q = 0; q < 4; q++) {
            float4 f = xp[q];
            v[4*q+0] = f.x; v[4*q+1] = f.y; v[4*q+2] = f.z; v[4*q+3] = f.w;
        }
        float s = 0.f;
        #pragma unroll
        for (int q = 0; q < 16; q++) s += v[q];
        s += __shfl_xor_sync(0xffffffffu, s, 1);
        s += __shfl_xor_sync(0xffffffffu, s, 2);
        const float mean = s * (1.f / 64.f);
        float vs = 0.f;
        #pragma unroll
        for (int q = 0; q < 16; q++) { float d = v[q] - mean; vs += d * d; }
        vs += __shfl_xor_sync(0xffffffffu, vs, 1);
        vs += __shfl_xor_sync(0xffffffffu, vs, 2);
        const float rs = rsqrtf(vs * (1.f / 64.f) + 1e-5f);
        #pragma unroll
        for (int q = 0; q < 16; q++) {
            int d = sub * 16 + q;
            sh[tt * 65 + d] = (v[q] - mean) * rs * g1[d] + b1v[d];
        }
    }
    __syncthreads();

    const int tg = tid >> 4, cg = tid & 15;
    float acc[4][12];
    #pragma unroll
    for (int i = 0; i < 4; i++)
        #pragma unroll
        for (int m = 0; m < 12; m++) acc[i][m] = 0.f;

    for (int d = 0; d < 64; d++) {
        float hv[4];
        #pragma unroll
        for (int i = 0; i < 4; i++) hv[i] = sh[(tg * 4 + i) * 65 + d];
        #pragma unroll
        for (int m = 0; m < 12; m++) {
            float w = sW[d * 192 + cg + 16 * m];
            #pragma unroll
            for (int i = 0; i < 4; i++) acc[i][m] += hv[i] * w;
        }
    }
    #pragma unroll
    for (int i = 0; i < 4; i++) {
        const size_t n = (size_t)(t0 + tg * 4 + i);
        #pragma unroll
        for (int m = 0; m < 12; m++) {
            const int col = cg + 16 * m;
            const float val = acc[i][m] + bp[col];
            if (m < 8) {
                __nv_bfloat16 hv = __float2bfloat16(val);
                g_qkh[n * 128 + col] = hv;
                g_qkl[n * 128 + col] = __float2bfloat16(val - __bfloat162float(hv));
            } else {
                g_v[n * 64 + (col - 128)] = __float2half(val);
            }
        }
    }
}

// ===========================================================================
// Helpers for mma.sync path
// ===========================================================================
__device__ __forceinline__ uint32_t smem_u32(const void* p) {
    uint32_t a;
    asm("{ .reg .u64 t; cvta.to.shared.u64 t, %1; cvt.u32.u64 %0, t; }"
        : "=r"(a) : "l"(p));
    return a;
}
__device__ __forceinline__ uint32_t packh2(float a, float b) {
    __half2 h = __floats2half2_rn(a, b);
    return *reinterpret_cast<uint32_t*>(&h);
}

#define LDSM_X4(r0,r1,r2,r3, addr) \
    asm volatile("ldmatrix.sync.aligned.m8n8.x4.shared.b16 {%0,%1,%2,%3}, [%4];" \
        : "=r"(r0), "=r"(r1), "=r"(r2), "=r"(r3) : "r"(addr))
#define LDSM_X4_T(r0,r1,r2,r3, addr) \
    asm volatile("ldmatrix.sync.aligned.m8n8.x4.trans.shared.b16 {%0,%1,%2,%3}, [%4];" \
        : "=r"(r0), "=r"(r1), "=r"(r2), "=r"(r3) : "r"(addr))

__device__ __forceinline__ void mma_bf(float* d, uint32_t a0, uint32_t a1,
                                       uint32_t a2, uint32_t a3,
                                       uint32_t b0, uint32_t b1) {
    asm volatile(
        "mma.sync.aligned.m16n8k16.row.col.f32.bf16.bf16.f32 "
        "{%0,%1,%2,%3}, {%4,%5,%6,%7}, {%8,%9}, {%0,%1,%2,%3};"
        : "+f"(d[0]), "+f"(d[1]), "+f"(d[2]), "+f"(d[3])
        : "r"(a0), "r"(a1), "r"(a2), "r"(a3), "r"(b0), "r"(b1));
}
__device__ __forceinline__ void mma_fp(float* d, uint32_t a0, uint32_t a1,
                                       uint32_t a2, uint32_t a3,
                                       uint32_t b0, uint32_t b1) {
    asm volatile(
        "mma.sync.aligned.m16n8k16.row.col.f32.f16.f16.f32 "
        "{%0,%1,%2,%3}, {%4,%5,%6,%7}, {%8,%9}, {%0,%1,%2,%3};"
        : "+f"(d[0]), "+f"(d[1]), "+f"(d[2]), "+f"(d[3])
        : "r"(a0), "r"(a1), "r"(a2), "r"(a3), "r"(b0), "r"(b1));
}

#define CPA(dst, src) asm volatile("cp.async.cg.shared.global [%0], [%1], 16;" \
        :: "r"(dst), "l"(src) : "memory")
#define CPC() asm volatile("cp.async.commit_group;" ::: "memory")
#define CPW(n) asm volatile("cp.async.wait_group %0;" :: "n"(n) : "memory")

// smem byte layout for k2
#define QPITCH 272          // [Qh 128B | Ql 128B | pad]
#define KPITCH 272          // [Kh 128B | Kl 128B | pad]
#define VPITCH 144          // [V 128B | pad]
#define SM_Q   0
#define SM_KB  (128 * QPITCH)               // 34816
#define KBUF   (64 * KPITCH)                // 17408
#define SM_VB  (SM_KB + 2 * KBUF)           // 69632
#define VBUF   (64 * VPITCH)                // 9216
#define SM2_TOTAL (SM_VB + 2 * VBUF)        // 88064

// ===========================================================================
// Kernel 2: flash attention.  QK: bf16 3-term hi/lo.  PV: fp16 1-term.
// Online max softmax.  cp.async double-buffered K/V.
// 256 threads (8 warps x 16 q-rows).  grid (S/128, B*H).
// ===========================================================================
__global__ __launch_bounds__(256, 2)
void k2_attn_mma()
{
    extern __shared__ char smc[];
    const uint32_t sb = smem_u32(smc);

    const int tid  = threadIdx.x;
    const int wid  = tid >> 5;
    const int lane = tid & 31;
    const int b = blockIdx.y >> 3, h = blockIdx.y & 7;
    const int q0 = blockIdx.x * 128;
    const int m0 = wid * 16;

    const int g  = lane >> 3;
    const int lr = lane & 7;

    // per-lane ldmatrix offsets
    const uint32_t aQ   = sb + SM_Q + (uint32_t)(m0 + (g & 1) * 8 + lr) * QPITCH + (g >> 1) * 16;
    const uint32_t kOff = (uint32_t)((g >> 1) * 8 + lr) * KPITCH + (g & 1) * 16;
    const uint32_t vOff = (uint32_t)((g & 1) * 8 + lr) * VPITCH + (g >> 1) * 16;

    // ---- prologue: cp.async Q tile + K/V tile 0 ----
    {
        // Q: 128 rows x 16 chunks
        for (int it = tid; it < 2048; it += 256) {
            const int row = it >> 4, c = it & 15;
            const size_t n = ((size_t)(b * SS + q0 + row)) * HH + h;
            const char* src = (c < 8)
                ? (const char*)(g_qkh + n * 128 + c * 8)
                : (const char*)(g_qkl + n * 128 + (c - 8) * 8);
            CPA(sb + SM_Q + row * QPITCH + c * 16, src);
        }
        // K tile 0
        for (int it = tid; it < 1024; it += 256) {
            const int row = it >> 4, c = it & 15;
            const size_t n = ((size_t)(b * SS + row)) * HH + h;
            const char* src = (c < 8)
                ? (const char*)(g_qkh + n * 128 + 64 + c * 8)
                : (const char*)(g_qkl + n * 128 + 64 + (c - 8) * 8);
            CPA(sb + SM_KB + row * KPITCH + c * 16, src);
        }
        // V tile 0
        for (int it = tid; it < 512; it += 256) {
            const int row = it >> 3, c = it & 7;
            const size_t n = ((size_t)(b * SS + row)) * HH + h;
            CPA(sb + SM_VB + row * VPITCH + c * 16, (const char*)(g_v + n * 64 + c * 8));
        }
        CPC();
    }

    float o[8][4];
    #pragma unroll
    for (int j = 0; j < 8; j++)
        #pragma unroll
        for (int e = 0; e < 4; e++) o[j][e] = 0.f;
    float mrow0 = -INFINITY, mrow1 = -INFINITY;
    float lsum0 = 0.f, lsum1 = 0.f;

    for (int kt = 0; kt < SS / 64; kt++) {
        __syncthreads();   // all warps done reading the buffer we're about to overwrite
        if (kt + 1 < SS / 64) {
            const int k0n = (kt + 1) * 64;
            const uint32_t dK = sb + SM_KB + ((kt + 1) & 1) * KBUF;
            const uint32_t dV = sb + SM_VB + ((kt + 1) & 1) * VBUF;
            for (int it = tid; it < 1024; it += 256) {
                const int row = it >> 4, c = it & 15;
                const size_t n = ((size_t)(b * SS + k0n + row)) * HH + h;
                const char* src = (c < 8)
                    ? (const char*)(g_qkh + n * 128 + 64 + c * 8)
                    : (const char*)(g_qkl + n * 128 + 64 + (c - 8) * 8);
                CPA(dK + row * KPITCH + c * 16, src);
            }
            for (int it = tid; it < 512; it += 256) {
                const int row = it >> 3, c = it & 7;
                const size_t n = ((size_t)(b * SS + k0n + row)) * HH + h;
                CPA(dV + row * VPITCH + c * 16, (const char*)(g_v + n * 64 + c * 8));
            }
            CPC();
            CPW(1);        // current tile (kt) complete
        } else {
            CPW(0);
        }
        __syncthreads();   // data visible to all warps

        const uint32_t bK = sb + SM_KB + (kt & 1) * KBUF + kOff;
        const uint32_t bV = sb + SM_VB + (kt & 1) * VBUF + vOff;

        // ---- S = Qh*Kh + Ql*Kh + Qh*Kl ----
        float s[8][4];
        #pragma unroll
        for (int j = 0; j < 8; j++)
            #pragma unroll
            for (int e = 0; e < 4; e++) s[j][e] = 0.f;

        #pragma unroll
        for (int ks = 0; ks < 4; ks++) {
            uint32_t qh0, qh1, qh2, qh3, ql0, ql1, ql2, ql3;
            LDSM_X4(qh0, qh1, qh2, qh3, aQ + ks * 32);
            LDSM_X4(ql0, ql1, ql2, ql3, aQ + 128 + ks * 32);
            #pragma unroll
            for (int j = 0; j < 4; j++) {
                uint32_t kh0, kh1, kh2, kh3, kl0, kl1, kl2, kl3;
                LDSM_X4(kh0, kh1, kh2, kh3, bK + j * (16 * KPITCH) + ks * 32);
                LDSM_X4(kl0, kl1, kl2, kl3, bK + j * (16 * KPITCH) + 128 + ks * 32);
                mma_bf(s[2*j],     qh0, qh1, qh2, qh3, kh0, kh1);
                mma_bf(s[2*j + 1], qh0, qh1, qh2, qh3, kh2, kh3);
                mma_bf(s[2*j],     ql0, ql1, ql2, ql3, kh0, kh1);
                mma_bf(s[2*j + 1], ql0, ql1, ql2, ql3, kh2, kh3);
                mma_bf(s[2*j],     qh0, qh1, qh2, qh3, kl0, kl1);
                mma_bf(s[2*j + 1], qh0, qh1, qh2, qh3, kl2, kl3);
            }
        }

        // ---- online softmax (rows r and r+8 per thread) ----
        float t0 = -INFINITY, t1 = -INFINITY;
        #pragma unroll
        for (int j = 0; j < 8; j++) {
            t0 = fmaxf(t0, fmaxf(s[j][0], s[j][1]));
            t1 = fmaxf(t1, fmaxf(s[j][2], s[j][3]));
        }
        t0 = fmaxf(t0, __shfl_xor_sync(0xffffffffu, t0, 1));
        t0 = fmaxf(t0, __shfl_xor_sync(0xffffffffu, t0, 2));
        t1 = fmaxf(t1, __shfl_xor_sync(0xffffffffu, t1, 1));
        t1 = fmaxf(t1, __shfl_xor_sync(0xffffffffu, t1, 2));
        const float mn0 = fmaxf(mrow0, t0);
        const float mn1 = fmaxf(mrow1, t1);
        const float sc0 = __expf(mrow0 - mn0);
        const float sc1 = __expf(mrow1 - mn1);
        mrow0 = mn0; mrow1 = mn1;

        float acc0 = 0.f, acc1 = 0.f;
        #pragma unroll
        for (int j = 0; j < 8; j++) {
            s[j][0] = __expf(s[j][0] - mn0);
            s[j][1] = __expf(s[j][1] - mn0);
            s[j][2] = __expf(s[j][2] - mn1);
            s[j][3] = __expf(s[j][3] - mn1);
            acc0 += s[j][0] + s[j][1];
            acc1 += s[j][2] + s[j][3];
        }
        lsum0 = lsum0 * sc0 + acc0;
        lsum1 = lsum1 * sc1 + acc1;
        #pragma unroll
        for (int j = 0; j < 8; j++) {
            o[j][0] *= sc0; o[j][1] *= sc0;
            o[j][2] *= sc1; o[j][3] *= sc1;
        }

        // ---- O += P * V  (fp16 single-pass) ----
        #pragma unroll
        for (int kk = 0; kk < 4; kk++) {
            const uint32_t p0 = packh2(s[2*kk][0],     s[2*kk][1]);
            const uint32_t p1 = packh2(s[2*kk][2],     s[2*kk][3]);
            const uint32_t p2 = packh2(s[2*kk + 1][0], s[2*kk + 1][1]);
            const uint32_t p3 = packh2(s[2*kk + 1][2], s[2*kk + 1][3]);
            #pragma unroll
            for (int j = 0; j < 4; j++) {
                uint32_t v0, v1, v2, v3;
                LDSM_X4_T(v0, v1, v2, v3, bV + kk * (16 * VPITCH) + j * 32);
                mma_fp(o[2*j],     p0, p1, p2, p3, v0, v1);
                mma_fp(o[2*j + 1], p0, p1, p2, p3, v2, v3);
            }
        }
    }

    // ---- epilogue ----
    lsum0 += __shfl_xor_sync(0xffffffffu, lsum0, 1);
    lsum0 += __shfl_xor_sync(0xffffffffu, lsum0, 2);
    lsum1 += __shfl_xor_sync(0xffffffffu, lsum1, 1);
    lsum1 += __shfl_xor_sync(0xffffffffu, lsum1, 2);
    const float inv0 = 1.f / lsum0, inv1 = 1.f / lsum1;

    const int r0 = q0 + m0 + (lane >> 2);
    const int c0 = (lane & 3) * 2;
    const size_t n0 = ((size_t)(b * SS + r0)) * HH + h;
    const size_t n1 = ((size_t)(b * SS + r0 + 8)) * HH + h;
    #pragma unroll
    for (int j = 0; j < 8; j++) {
        float2 v0 = make_float2(o[j][0] * inv0, o[j][1] * inv0);
        float2 v1 = make_float2(o[j][2] * inv1, o[j][3] * inv1);
        *(float2*)(g_attn + n0 * 64 + 8 * j + c0) = v0;
        *(float2*)(g_attn + n1 * 64 + 8 * j + c0) = v1;
    }
}

// ===========================================================================
// Kernel 3: LN2 + MLP (gelu exact) + residual.  32 tokens/block, 256 threads.
// ===========================================================================
__global__ __launch_bounds__(256)
void k3_ln_mlp(const float* __restrict__ x,
               const float* __restrict__ g2, const float* __restrict__ b2v,
               const float* __restrict__ W1, const float* __restrict__ b1m,
               const float* __restrict__ W2, const float* __restrict__ b2m,
               float* __restrict__ out)
{
    extern __shared__ float sm3[];
    float* sW1 = sm3;                   // 64*256
    float* sW2 = sW1 + 64 * 256;        // 256*64
    float* sa  = sW2 + 256 * 64;        // 32*65
    float* sh1 = sa + 32 * 65;          // 32*256

    const int tid = threadIdx.x;
    const int t0 = blockIdx.x * 32;

    for (int i = tid; i < 64 * 256; i += 256) sW1[i] = W1[i];
    for (int i = tid; i < 256 * 64; i += 256) sW2[i] = W2[i];

    {
        const int tt = tid >> 3, sub = tid & 7;
        const size_t base = ((size_t)(t0 + tt)) * 64 + sub * 8;
        float v[8];
        const float4* ap = (const float4*)(g_attn + base);
        float4 f0 = ap[0], f1 = ap[1];
        v[0]=f0.x; v[1]=f0.y; v[2]=f0.z; v[3]=f0.w;
        v[4]=f1.x; v[5]=f1.y; v[6]=f1.z; v[7]=f1.w;
        float s = 0.f;
        #pragma unroll
        for (int q = 0; q < 8; q++) s += v[q];
        s += __shfl_xor_sync(0xffffffffu, s, 1);
        s += __shfl_xor_sync(0xffffffffu, s, 2);
        s += __shfl_xor_sync(0xffffffffu, s, 4);
        const float mean = s * (1.f / 64.f);
        float vs = 0.f;
        #pragma unroll
        for (int q = 0; q < 8; q++) { float d = v[q] - mean; vs += d * d; }
        vs += __shfl_xor_sync(0xffffffffu, vs, 1);
        vs += __shfl_xor_sync(0xffffffffu, vs, 2);
        vs += __shfl_xor_sync(0xffffffffu, vs, 4);
        const float rs = rsqrtf(vs * (1.f / 64.f) + 1e-5f);
        #pragma unroll
        for (int q = 0; q < 8; q++) {
            int d = sub * 8 + q;
            sa[tt * 65 + d] = (v[q] - mean) * rs * g2[d] + b2v[d];
        }
    }
    __syncthreads();

    const int tg = tid >> 5, cg = tid & 31;
    {
        float a1[4][8];
        #pragma unroll
        for (int i = 0; i < 4; i++)
            #pragma unroll
            for (int mcol = 0; mcol < 8; mcol++) a1[i][mcol] = 0.f;
        for (int d = 0; d < 64; d++) {
            float hv[4];
            #pragma unroll
            for (int i = 0; i < 4; i++) hv[i] = sa[(tg * 4 + i) * 65 + d];
            #pragma unroll
            for (int mcol = 0; mcol < 8; mcol++) {
                float w = sW1[d * 256 + cg + 32 * mcol];
                #pragma unroll
                for (int i = 0; i < 4; i++) a1[i][mcol] += hv[i] * w;
            }
        }
        #pragma unroll
        for (int i = 0; i < 4; i++)
            #pragma unroll
            for (int mcol = 0; mcol < 8; mcol++) {
                int col = cg + 32 * mcol;
                float z = a1[i][mcol] + b1m[col];
                float ge = 0.5f * z * (1.f + erff(z * 0.70710678118654752f));
                sh1[(tg * 4 + i) * 256 + col] = ge;
            }
    }
    __syncthreads();

    {
        float a2[4][2];
        #pragma unroll
        for (int i = 0; i < 4; i++) { a2[i][0] = 0.f; a2[i][1] = 0.f; }
        for (int k = 0; k < 256; k++) {
            float w0 = sW2[k * 64 + cg];
            float w1 = sW2[k * 64 + cg + 32];
            #pragma unroll
            for (int i = 0; i < 4; i++) {
                float hv = sh1[(tg * 4 + i) * 256 + k];
                a2[i][0] += hv * w0;
                a2[i][1] += hv * w1;
            }
        }
        #pragma unroll
        for (int i = 0; i < 4; i++) {
            const size_t n = (size_t)(t0 + tg * 4 + i);
            #pragma unroll
            for (int jj = 0; jj < 2; jj++) {
                int col = cg + 32 * jj;
                out[n * 64 + col] = a2[i][jj] + b2m[col] + x[n * 64 + col];
            }
        }
    }
}

// ===========================================================================
extern "C" void kernel_launch(void* const* d_in, const int* in_sizes, int n_in,
                              void* d_out, int out_size)
{
    const float* x    = (const float*)d_in[0];
    const float* ln1g = (const float*)d_in[1];
    const float* ln1b = (const float*)d_in[2];
    const float* Wp   = (const float*)d_in[3];
    const float* bp   = (const float*)d_in[4];
    const float* ln2g = (const float*)d_in[5];
    const float* ln2b = (const float*)d_in[6];
    const float* W1   = (const float*)d_in[7];
    const float* b1   = (const float*)d_in[8];
    const float* W2   = (const float*)d_in[9];
    const float* b2   = (const float*)d_in[10];
    float* out = (float*)d_out;

    const int smem1 = (64 * 192 + 64 * 65) * 4;
    const int smem2 = SM2_TOTAL;
    const int smem3 = (64 * 256 + 256 * 64 + 32 * 65 + 32 * 256) * 4;

    cudaFuncSetAttribute(k1_ln_qkv,   cudaFuncAttributeMaxDynamicSharedMemorySize, smem1);
    cudaFuncSetAttribute(k2_attn_mma, cudaFuncAttributeMaxDynamicSharedMemorySize, smem2);
    cudaFuncSetAttribute(k3_ln_mlp,   cudaFuncAttributeMaxDynamicSharedMemorySize, smem3);

    k1_ln_qkv<<<NTOK / 64, 256, smem1>>>(x, ln1g, ln1b, Wp, bp);
    k2_attn_mma<<<dim3(SS / 128, BB * HH), 256, smem2>>>();
    k3_ln_mlp<<<NTOK / 32, 256, smem3>>>(x, ln2g, ln2b, W1, b1, W2, b2, out);
}

// round 5
// speedup vs baseline: 8.1233x; 1.4904x over previous
#include <cuda_runtime.h>
#include <cuda_bf16.h>
#include <cuda_fp16.h>
#include <math.h>
#include <stdint.h>

#define BB 4
#define SS 2048
#define HH 8
#define DD 64
#define NTOK (BB*SS*HH)   // 65536 tokens

// Scratch (allocation-free rule: __device__ globals)
__device__ __nv_bfloat16 g_qkh[(size_t)NTOK * 128];  // [n][128] q|k hi parts
__device__ __nv_bfloat16 g_qkl[(size_t)NTOK * 128];  // [n][128] q|k lo parts
__device__ __half        g_v  [(size_t)NTOK * 64];   // [n][64]  v fp16
__device__ float         g_attn[(size_t)NTOK * 64];  // [n][64]  attention out
__device__ __half        g_h1 [(size_t)NTOK * 256];  // [n][256] gelu(h1) fp16
// Pre-transposed / split weights
__device__ __nv_bfloat16 g_w1h[256 * 64];            // W1^T [n][k] hi
__device__ __nv_bfloat16 g_w1l[256 * 64];            // W1^T [n][k] lo
__device__ __half        g_w2h[64 * 256];            // W2^T [n][k] hi (fp16)
__device__ __half        g_w2l[64 * 256];            // W2^T [n][k] lo (fp16)

// ===========================================================================
// Kernel 0: weight prep (transpose + split).  64 blocks x 256 threads.
// ===========================================================================
__global__ __launch_bounds__(256)
void kprep(const float* __restrict__ W1, const float* __restrict__ W2)
{
    const int i = blockIdx.x * 256 + threadIdx.x;   // 0..16383
    {
        const int k = i >> 8, n = i & 255;          // W1 [64][256]
        const float v = W1[k * 256 + n];
        __nv_bfloat16 hv = __float2bfloat16(v);
        g_w1h[n * 64 + k] = hv;
        g_w1l[n * 64 + k] = __float2bfloat16(v - __bfloat162float(hv));
    }
    {
        const int k = i >> 6, n = i & 63;           // W2 [256][64]
        const float v = W2[k * 64 + n];
        __half hv = __float2half(v);
        g_w2h[n * 256 + k] = hv;
        g_w2l[n * 256 + k] = __float2half(v - __half2float(hv));
    }
}

// ===========================================================================
// Kernel 1: LN1 + QKV projection.  64 tokens/block, 256 threads. (unchanged)
// ===========================================================================
__global__ __launch_bounds__(256)
void k1_ln_qkv(const float* __restrict__ x,
               const float* __restrict__ g1, const float* __restrict__ b1v,
               const float* __restrict__ Wp, const float* __restrict__ bp)
{
    extern __shared__ float sm1[];
    float* sW = sm1;              // 64*192
    float* sh = sm1 + 64 * 192;   // 64*65

    const int tid = threadIdx.x;
    const int t0  = blockIdx.x * 64;

    for (int i = tid; i < 64 * 192; i += 256) sW[i] = Wp[i];

    {
        const int tt = tid >> 2, sub = tid & 3;
        const size_t base = ((size_t)(t0 + tt)) * 64 + sub * 16;
        float v[16];
        const float4* xp = (const float4*)(x + base);
        #pragma unroll
        for (int q = 0; q < 4; q++) {
            float4 f = xp[q];
            v[4*q+0] = f.x; v[4*q+1] = f.y; v[4*q+2] = f.z; v[4*q+3] = f.w;
        }
        float s = 0.f;
        #pragma unroll
        for (int q = 0; q < 16; q++) s += v[q];
        s += __shfl_xor_sync(0xffffffffu, s, 1);
        s += __shfl_xor_sync(0xffffffffu, s, 2);
        const float mean = s * (1.f / 64.f);
        float vs = 0.f;
        #pragma unroll
        for (int q = 0; q < 16; q++) { float d = v[q] - mean; vs += d * d; }
        vs += __shfl_xor_sync(0xffffffffu, vs, 1);
        vs += __shfl_xor_sync(0xffffffffu, vs, 2);
        const float rs = rsqrtf(vs * (1.f / 64.f) + 1e-5f);
        #pragma unroll
        for (int q = 0; q < 16; q++) {
            int d = sub * 16 + q;
            sh[tt * 65 + d] = (v[q] - mean) * rs * g1[d] + b1v[d];
        }
    }
    __syncthreads();

    const int tg = tid >> 4, cg = tid & 15;
    float acc[4][12];
    #pragma unroll
    for (int i = 0; i < 4; i++)
        #pragma unroll
        for (int m = 0; m < 12; m++) acc[i][m] = 0.f;

    for (int d = 0; d < 64; d++) {
        float hv[4];
        #pragma unroll
        for (int i = 0; i < 4; i++) hv[i] = sh[(tg * 4 + i) * 65 + d];
        #pragma unroll
        for (int m = 0; m < 12; m++) {
            float w = sW[d * 192 + cg + 16 * m];
            #pragma unroll
            for (int i = 0; i < 4; i++) acc[i][m] += hv[i] * w;
        }
    }
    #pragma unroll
    for (int i = 0; i < 4; i++) {
        const size_t n = (size_t)(t0 + tg * 4 + i);
        #pragma unroll
        for (int m = 0; m < 12; m++) {
            const int col = cg + 16 * m;
            const float val = acc[i][m] + bp[col];
            if (m < 8) {
                __nv_bfloat16 hv = __float2bfloat16(val);
                g_qkh[n * 128 + col] = hv;
                g_qkl[n * 128 + col] = __float2bfloat16(val - __bfloat162float(hv));
            } else {
                g_v[n * 64 + (col - 128)] = __float2half(val);
            }
        }
    }
}

// ===========================================================================
// Helpers for mma.sync path
// ===========================================================================
__device__ __forceinline__ uint32_t smem_u32(const void* p) {
    uint32_t a;
    asm("{ .reg .u64 t; cvta.to.shared.u64 t, %1; cvt.u32.u64 %0, t; }"
        : "=r"(a) : "l"(p));
    return a;
}
__device__ __forceinline__ uint32_t packh2(float a, float b) {
    __half2 h = __floats2half2_rn(a, b);
    return *reinterpret_cast<uint32_t*>(&h);
}
__device__ __forceinline__ uint32_t packbf2(float a, float b) {
    __nv_bfloat16 ha = __float2bfloat16(a), hb = __float2bfloat16(b);
    return (uint32_t)__bfloat16_as_ushort(ha) | ((uint32_t)__bfloat16_as_ushort(hb) << 16);
}

#define LDSM_X4(r0,r1,r2,r3, addr) \
    asm volatile("ldmatrix.sync.aligned.m8n8.x4.shared.b16 {%0,%1,%2,%3}, [%4];" \
        : "=r"(r0), "=r"(r1), "=r"(r2), "=r"(r3) : "r"(addr))
#define LDSM_X4_T(r0,r1,r2,r3, addr) \
    asm volatile("ldmatrix.sync.aligned.m8n8.x4.trans.shared.b16 {%0,%1,%2,%3}, [%4];" \
        : "=r"(r0), "=r"(r1), "=r"(r2), "=r"(r3) : "r"(addr))

__device__ __forceinline__ void mma_bf(float* d, uint32_t a0, uint32_t a1,
                                       uint32_t a2, uint32_t a3,
                                       uint32_t b0, uint32_t b1) {
    asm volatile(
        "mma.sync.aligned.m16n8k16.row.col.f32.bf16.bf16.f32 "
        "{%0,%1,%2,%3}, {%4,%5,%6,%7}, {%8,%9}, {%0,%1,%2,%3};"
        : "+f"(d[0]), "+f"(d[1]), "+f"(d[2]), "+f"(d[3])
        : "r"(a0), "r"(a1), "r"(a2), "r"(a3), "r"(b0), "r"(b1));
}
__device__ __forceinline__ void mma_fp(float* d, uint32_t a0, uint32_t a1,
                                       uint32_t a2, uint32_t a3,
                                       uint32_t b0, uint32_t b1) {
    asm volatile(
        "mma.sync.aligned.m16n8k16.row.col.f32.f16.f16.f32 "
        "{%0,%1,%2,%3}, {%4,%5,%6,%7}, {%8,%9}, {%0,%1,%2,%3};"
        : "+f"(d[0]), "+f"(d[1]), "+f"(d[2]), "+f"(d[3])
        : "r"(a0), "r"(a1), "r"(a2), "r"(a3), "r"(b0), "r"(b1));
}

#define CPA(dst, src) asm volatile("cp.async.cg.shared.global [%0], [%1], 16;" \
        :: "r"(dst), "l"(src) : "memory")
#define CPC() asm volatile("cp.async.commit_group;" ::: "memory")
#define CPW(n) asm volatile("cp.async.wait_group %0;" :: "n"(n) : "memory")

// smem byte layout for k2
#define QPITCH 272          // [Qh 128B | Ql 128B | pad]
#define KPITCH 272          // [Kh 128B | Kl 128B | pad]
#define VPITCH 144          // [V 128B | pad]
#define SM_Q   0
#define SM_KB  (128 * QPITCH)               // 34816
#define KBUF   (64 * KPITCH)                // 17408
#define SM_VB  (SM_KB + 2 * KBUF)           // 69632
#define VBUF   (64 * VPITCH)                // 9216
#define SM2_TOTAL (SM_VB + 2 * VBUF)        // 88064

// ===========================================================================
// Kernel 2: flash attention.  QK: bf16 3-term hi/lo.  PV: fp16 1-term.
// (unchanged from R4)
// ===========================================================================
__global__ __launch_bounds__(256, 2)
void k2_attn_mma()
{
    extern __shared__ char smc[];
    const uint32_t sb = smem_u32(smc);

    const int tid  = threadIdx.x;
    const int wid  = tid >> 5;
    const int lane = tid & 31;
    const int b = blockIdx.y >> 3, h = blockIdx.y & 7;
    const int q0 = blockIdx.x * 128;
    const int m0 = wid * 16;

    const int g  = lane >> 3;
    const int lr = lane & 7;

    const uint32_t aQ   = sb + SM_Q + (uint32_t)(m0 + (g & 1) * 8 + lr) * QPITCH + (g >> 1) * 16;
    const uint32_t kOff = (uint32_t)((g >> 1) * 8 + lr) * KPITCH + (g & 1) * 16;
    const uint32_t vOff = (uint32_t)((g & 1) * 8 + lr) * VPITCH + (g >> 1) * 16;

    {
        for (int it = tid; it < 2048; it += 256) {
            const int row = it >> 4, c = it & 15;
            const size_t n = ((size_t)(b * SS + q0 + row)) * HH + h;
            const char* src = (c < 8)
                ? (const char*)(g_qkh + n * 128 + c * 8)
                : (const char*)(g_qkl + n * 128 + (c - 8) * 8);
            CPA(sb + SM_Q + row * QPITCH + c * 16, src);
        }
        for (int it = tid; it < 1024; it += 256) {
            const int row = it >> 4, c = it & 15;
            const size_t n = ((size_t)(b * SS + row)) * HH + h;
            const char* src = (c < 8)
                ? (const char*)(g_qkh + n * 128 + 64 + c * 8)
                : (const char*)(g_qkl + n * 128 + 64 + (c - 8) * 8);
            CPA(sb + SM_KB + row * KPITCH + c * 16, src);
        }
        for (int it = tid; it < 512; it += 256) {
            const int row = it >> 3, c = it & 7;
            const size_t n = ((size_t)(b * SS + row)) * HH + h;
            CPA(sb + SM_VB + row * VPITCH + c * 16, (const char*)(g_v + n * 64 + c * 8));
        }
        CPC();
    }

    float o[8][4];
    #pragma unroll
    for (int j = 0; j < 8; j++)
        #pragma unroll
        for (int e = 0; e < 4; e++) o[j][e] = 0.f;
    float mrow0 = -INFINITY, mrow1 = -INFINITY;
    float lsum0 = 0.f, lsum1 = 0.f;

    for (int kt = 0; kt < SS / 64; kt++) {
        __syncthreads();
        if (kt + 1 < SS / 64) {
            const int k0n = (kt + 1) * 64;
            const uint32_t dK = sb + SM_KB + ((kt + 1) & 1) * KBUF;
            const uint32_t dV = sb + SM_VB + ((kt + 1) & 1) * VBUF;
            for (int it = tid; it < 1024; it += 256) {
                const int row = it >> 4, c = it & 15;
                const size_t n = ((size_t)(b * SS + k0n + row)) * HH + h;
                const char* src = (c < 8)
                    ? (const char*)(g_qkh + n * 128 + 64 + c * 8)
                    : (const char*)(g_qkl + n * 128 + 64 + (c - 8) * 8);
                CPA(dK + row * KPITCH + c * 16, src);
            }
            for (int it = tid; it < 512; it += 256) {
                const int row = it >> 3, c = it & 7;
                const size_t n = ((size_t)(b * SS + k0n + row)) * HH + h;
                CPA(dV + row * VPITCH + c * 16, (const char*)(g_v + n * 64 + c * 8));
            }
            CPC();
            CPW(1);
        } else {
            CPW(0);
        }
        __syncthreads();

        const uint32_t bK = sb + SM_KB + (kt & 1) * KBUF + kOff;
        const uint32_t bV = sb + SM_VB + (kt & 1) * VBUF + vOff;

        float s[8][4];
        #pragma unroll
        for (int j = 0; j < 8; j++)
            #pragma unroll
            for (int e = 0; e < 4; e++) s[j][e] = 0.f;

        #pragma unroll
        for (int ks = 0; ks < 4; ks++) {
            uint32_t qh0, qh1, qh2, qh3, ql0, ql1, ql2, ql3;
            LDSM_X4(qh0, qh1, qh2, qh3, aQ + ks * 32);
            LDSM_X4(ql0, ql1, ql2, ql3, aQ + 128 + ks * 32);
            #pragma unroll
            for (int j = 0; j < 4; j++) {
                uint32_t kh0, kh1, kh2, kh3, kl0, kl1, kl2, kl3;
                LDSM_X4(kh0, kh1, kh2, kh3, bK + j * (16 * KPITCH) + ks * 32);
                LDSM_X4(kl0, kl1, kl2, kl3, bK + j * (16 * KPITCH) + 128 + ks * 32);
                mma_bf(s[2*j],     qh0, qh1, qh2, qh3, kh0, kh1);
                mma_bf(s[2*j + 1], qh0, qh1, qh2, qh3, kh2, kh3);
                mma_bf(s[2*j],     ql0, ql1, ql2, ql3, kh0, kh1);
                mma_bf(s[2*j + 1], ql0, ql1, ql2, ql3, kh2, kh3);
                mma_bf(s[2*j],     qh0, qh1, qh2, qh3, kl0, kl1);
                mma_bf(s[2*j + 1], qh0, qh1, qh2, qh3, kl2, kl3);
            }
        }

        float t0 = -INFINITY, t1 = -INFINITY;
        #pragma unroll
        for (int j = 0; j < 8; j++) {
            t0 = fmaxf(t0, fmaxf(s[j][0], s[j][1]));
            t1 = fmaxf(t1, fmaxf(s[j][2], s[j][3]));
        }
        t0 = fmaxf(t0, __shfl_xor_sync(0xffffffffu, t0, 1));
        t0 = fmaxf(t0, __shfl_xor_sync(0xffffffffu, t0, 2));
        t1 = fmaxf(t1, __shfl_xor_sync(0xffffffffu, t1, 1));
        t1 = fmaxf(t1, __shfl_xor_sync(0xffffffffu, t1, 2));
        const float mn0 = fmaxf(mrow0, t0);
        const float mn1 = fmaxf(mrow1, t1);
        const float sc0 = __expf(mrow0 - mn0);
        const float sc1 = __expf(mrow1 - mn1);
        mrow0 = mn0; mrow1 = mn1;

        float acc0 = 0.f, acc1 = 0.f;
        #pragma unroll
        for (int j = 0; j < 8; j++) {
            s[j][0] = __expf(s[j][0] - mn0);
            s[j][1] = __expf(s[j][1] - mn0);
            s[j][2] = __expf(s[j][2] - mn1);
            s[j][3] = __expf(s[j][3] - mn1);
            acc0 += s[j][0] + s[j][1];
            acc1 += s[j][2] + s[j][3];
        }
        lsum0 = lsum0 * sc0 + acc0;
        lsum1 = lsum1 * sc1 + acc1;
        #pragma unroll
        for (int j = 0; j < 8; j++) {
            o[j][0] *= sc0; o[j][1] *= sc0;
            o[j][2] *= sc1; o[j][3] *= sc1;
        }

        #pragma unroll
        for (int kk = 0; kk < 4; kk++) {
            const uint32_t p0 = packh2(s[2*kk][0],     s[2*kk][1]);
            const uint32_t p1 = packh2(s[2*kk][2],     s[2*kk][3]);
            const uint32_t p2 = packh2(s[2*kk + 1][0], s[2*kk + 1][1]);
            const uint32_t p3 = packh2(s[2*kk + 1][2], s[2*kk + 1][3]);
            #pragma unroll
            for (int j = 0; j < 4; j++) {
                uint32_t v0, v1, v2, v3;
                LDSM_X4_T(v0, v1, v2, v3, bV + kk * (16 * VPITCH) + j * 32);
                mma_fp(o[2*j],     p0, p1, p2, p3, v0, v1);
                mma_fp(o[2*j + 1], p0, p1, p2, p3, v2, v3);
            }
        }
    }

    lsum0 += __shfl_xor_sync(0xffffffffu, lsum0, 1);
    lsum0 += __shfl_xor_sync(0xffffffffu, lsum0, 2);
    lsum1 += __shfl_xor_sync(0xffffffffu, lsum1, 1);
    lsum1 += __shfl_xor_sync(0xffffffffu, lsum1, 2);
    const float inv0 = 1.f / lsum0, inv1 = 1.f / lsum1;

    const int r0 = q0 + m0 + (lane >> 2);
    const int c0 = (lane & 3) * 2;
    const size_t n0 = ((size_t)(b * SS + r0)) * HH + h;
    const size_t n1 = ((size_t)(b * SS + r0 + 8)) * HH + h;
    #pragma unroll
    for (int j = 0; j < 8; j++) {
        float2 v0 = make_float2(o[j][0] * inv0, o[j][1] * inv0);
        float2 v1 = make_float2(o[j][2] * inv1, o[j][3] * inv1);
        *(float2*)(g_attn + n0 * 64 + 8 * j + c0) = v0;
        *(float2*)(g_attn + n1 * 64 + 8 * j + c0) = v1;
    }
}

// ===========================================================================
// Kernel 3a: LN2 + GEMM1 (bf16 3-term HMMA) + exact gelu -> g_h1 (fp16).
// 512 threads (16 warps), 128 tokens/block.  grid = NTOK/128.
// smem: sA [128][272] @0 ; sW1 [256][272] @34816.  total 104448.
// ===========================================================================
#define K3A_SW1 34816
#define K3A_TOTAL (K3A_SW1 + 256 * 272)   // 104448

__global__ __launch_bounds__(512)
void k3a_ln_fc1(const float* __restrict__ g2, const float* __restrict__ b2v,
                const float* __restrict__ b1m)
{
    extern __shared__ char smc[];
    const uint32_t sb = smem_u32(smc);
    const int tid = threadIdx.x;
    const int t0 = blockIdx.x * 128;

    // async-load W1T hi/lo: 256 rows x 16 chunks
    for (int it = tid; it < 4096; it += 512) {
        const int n = it >> 4, c = it & 15;
        const char* src = (c < 8)
            ? (const char*)(g_w1h + n * 64 + c * 8)
            : (const char*)(g_w1l + n * 64 + (c - 8) * 8);
        CPA(sb + K3A_SW1 + n * 272 + c * 16, src);
    }
    CPC();

    // LN2: 4 threads/token, 16 elems each; write split hi/lo into sA
    {
        const int tt = tid >> 2, sub = tid & 3;
        const size_t base = ((size_t)(t0 + tt)) * 64 + sub * 16;
        float v[16];
        const float4* ap = (const float4*)(g_attn + base);
        #pragma unroll
        for (int q = 0; q < 4; q++) {
            float4 f = ap[q];
            v[4*q+0] = f.x; v[4*q+1] = f.y; v[4*q+2] = f.z; v[4*q+3] = f.w;
        }
        float s = 0.f;
        #pragma unroll
        for (int q = 0; q < 16; q++) s += v[q];
        s += __shfl_xor_sync(0xffffffffu, s, 1);
        s += __shfl_xor_sync(0xffffffffu, s, 2);
        const float mean = s * (1.f / 64.f);
        float vs = 0.f;
        #pragma unroll
        for (int q = 0; q < 16; q++) { float d = v[q] - mean; vs += d * d; }
        vs += __shfl_xor_sync(0xffffffffu, vs, 1);
        vs += __shfl_xor_sync(0xffffffffu, vs, 2);
        const float rs = rsqrtf(vs * (1.f / 64.f) + 1e-5f);
        float r[16];
        #pragma unroll
        for (int q = 0; q < 16; q++) {
            const int d = sub * 16 + q;
            r[q] = (v[q] - mean) * rs * g2[d] + b2v[d];
        }
        uint32_t hw[8], lw[8];
        #pragma unroll
        for (int q = 0; q < 8; q++) {
            __nv_bfloat16 h0 = __float2bfloat16(r[2*q]),
                          h1 = __float2bfloat16(r[2*q+1]);
            hw[q] = (uint32_t)__bfloat16_as_ushort(h0) | ((uint32_t)__bfloat16_as_ushort(h1) << 16);
            lw[q] = packbf2(r[2*q]   - __bfloat162float(h0),
                            r[2*q+1] - __bfloat162float(h1));
        }
        char* dst = smc + tt * 272 + sub * 32;
        *(uint4*)(dst)            = make_uint4(hw[0], hw[1], hw[2], hw[3]);
        *(uint4*)(dst + 16)       = make_uint4(hw[4], hw[5], hw[6], hw[7]);
        *(uint4*)(dst + 128)      = make_uint4(lw[0], lw[1], lw[2], lw[3]);
        *(uint4*)(dst + 128 + 16) = make_uint4(lw[4], lw[5], lw[6], lw[7]);
    }
    CPW(0);
    __syncthreads();

    // GEMM1: warp w: tokens (w&7)*16.., cols (w>>3)*128..
    const int wid = tid >> 5, lane = tid & 31;
    const int g = lane >> 3, lr = lane & 7;
    const int tg = (wid & 7) * 16;
    const int n0 = (wid >> 3) * 128;

    const uint32_t aA = sb + (uint32_t)(tg + (g & 1) * 8 + lr) * 272 + (g >> 1) * 16;
    const uint32_t bW = sb + K3A_SW1 + (uint32_t)(n0 + (g >> 1) * 8 + lr) * 272 + (g & 1) * 16;

    float s[16][4];
    #pragma unroll
    for (int j = 0; j < 16; j++)
        #pragma unroll
        for (int e = 0; e < 4; e++) s[j][e] = 0.f;

    #pragma unroll
    for (int ks = 0; ks < 4; ks++) {
        uint32_t ah0, ah1, ah2, ah3, al0, al1, al2, al3;
        LDSM_X4(ah0, ah1, ah2, ah3, aA + ks * 32);
        LDSM_X4(al0, al1, al2, al3, aA + 128 + ks * 32);
        #pragma unroll
        for (int j = 0; j < 8; j++) {
            uint32_t wh0, wh1, wh2, wh3, wl0, wl1, wl2, wl3;
            LDSM_X4(wh0, wh1, wh2, wh3, bW + j * (16 * 272) + ks * 32);
            LDSM_X4(wl0, wl1, wl2, wl3, bW + j * (16 * 272) + 128 + ks * 32);
            mma_bf(s[2*j],     ah0, ah1, ah2, ah3, wh0, wh1);
            mma_bf(s[2*j + 1], ah0, ah1, ah2, ah3, wh2, wh3);
            mma_bf(s[2*j],     al0, al1, al2, al3, wh0, wh1);
            mma_bf(s[2*j + 1], al0, al1, al2, al3, wh2, wh3);
            mma_bf(s[2*j],     ah0, ah1, ah2, ah3, wl0, wl1);
            mma_bf(s[2*j + 1], ah0, ah1, ah2, ah3, wl2, wl3);
        }
    }

    // epilogue: +b1, exact gelu, fp16 store
    const int r0 = t0 + tg + (lane >> 2);
    const int c0 = 2 * (lane & 3);
    #pragma unroll
    for (int idx = 0; idx < 16; idx++) {
        const int col = n0 + (idx >> 1) * 16 + (idx & 1) * 8 + c0;
        const float bb0 = b1m[col], bb1 = b1m[col + 1];
        float z0 = s[idx][0] + bb0, z1 = s[idx][1] + bb1;
        float z2 = s[idx][2] + bb0, z3 = s[idx][3] + bb1;
        z0 = 0.5f * z0 * (1.f + erff(z0 * 0.70710678118654752f));
        z1 = 0.5f * z1 * (1.f + erff(z1 * 0.70710678118654752f));
        z2 = 0.5f * z2 * (1.f + erff(z2 * 0.70710678118654752f));
        z3 = 0.5f * z3 * (1.f + erff(z3 * 0.70710678118654752f));
        *(uint32_t*)(g_h1 + (size_t)r0 * 256 + col)       = packh2(z0, z1);
        *(uint32_t*)(g_h1 + (size_t)(r0 + 8) * 256 + col) = packh2(z2, z3);
    }
}

// ===========================================================================
// Kernel 3b: GEMM2 (fp16 2-term HMMA) + bias + residual -> out.
// 256 threads (8 warps), 128 tokens/block.  grid = NTOK/128.
// smem: sH [128][528] @0 ; sW2 [64][1040] @67584.  total 134144.
// ===========================================================================
#define K3B_SW2 67584
#define K3B_TOTAL (K3B_SW2 + 64 * 1040)   // 134144

__global__ __launch_bounds__(256)
void k3b_fc2(const float* __restrict__ x, const float* __restrict__ b2m,
             float* __restrict__ out)
{
    extern __shared__ char smc[];
    const uint32_t sb = smem_u32(smc);
    const int tid = threadIdx.x;
    const int t0 = blockIdx.x * 128;

    // async-load W2T hi/lo fp16: 64 rows x 64 chunks
    for (int it = tid; it < 4096; it += 256) {
        const int n = it >> 6, c = it & 63;
        const char* src = (c < 32)
            ? (const char*)(g_w2h + n * 256 + c * 8)
            : (const char*)(g_w2l + n * 256 + (c - 32) * 8);
        CPA(sb + K3B_SW2 + n * 1040 + ((c < 32) ? c * 16 : 512 + (c - 32) * 16), src);
    }
    // async-load H tile: 128 rows x 32 chunks
    for (int it = tid; it < 4096; it += 256) {
        const int row = it >> 5, c = it & 31;
        CPA(sb + row * 528 + c * 16,
            (const char*)(g_h1 + (size_t)(t0 + row) * 256 + c * 8));
    }
    CPC();
    CPW(0);
    __syncthreads();

    const int wid = tid >> 5, lane = tid & 31;
    const int g = lane >> 3, lr = lane & 7;
    const int tg = wid * 16;

    const uint32_t aH = sb + (uint32_t)(tg + (g & 1) * 8 + lr) * 528 + (g >> 1) * 16;
    const uint32_t bW = sb + K3B_SW2 + (uint32_t)((g >> 1) * 8 + lr) * 1040 + (g & 1) * 16;

    float o[8][4];
    #pragma unroll
    for (int j = 0; j < 8; j++)
        #pragma unroll
        for (int e = 0; e < 4; e++) o[j][e] = 0.f;

    #pragma unroll
    for (int ks = 0; ks < 16; ks++) {
        uint32_t ah0, ah1, ah2, ah3;
        LDSM_X4(ah0, ah1, ah2, ah3, aH + ks * 32);
        #pragma unroll
        for (int j = 0; j < 4; j++) {
            uint32_t wh0, wh1, wh2, wh3, wl0, wl1, wl2, wl3;
            LDSM_X4(wh0, wh1, wh2, wh3, bW + j * (16 * 1040) + ks * 32);
            LDSM_X4(wl0, wl1, wl2, wl3, bW + j * (16 * 1040) + 512 + ks * 32);
            mma_fp(o[2*j],     ah0, ah1, ah2, ah3, wh0, wh1);
            mma_fp(o[2*j + 1], ah0, ah1, ah2, ah3, wh2, wh3);
            mma_fp(o[2*j],     ah0, ah1, ah2, ah3, wl0, wl1);
            mma_fp(o[2*j + 1], ah0, ah1, ah2, ah3, wl2, wl3);
        }
    }

    // epilogue: + b2 + residual x
    const int r0 = t0 + tg + (lane >> 2);
    const int c0 = 2 * (lane & 3);
    #pragma unroll
    for (int idx = 0; idx < 8; idx++) {
        const int col = (idx >> 1) * 16 + (idx & 1) * 8 + c0;
        const float bb0 = b2m[col], bb1 = b2m[col + 1];
        const size_t na = (size_t)r0 * 64 + col;
        const size_t nb = (size_t)(r0 + 8) * 64 + col;
        float2 xa = *(const float2*)(x + na);
        float2 xb = *(const float2*)(x + nb);
        *(float2*)(out + na) = make_float2(o[idx][0] + bb0 + xa.x, o[idx][1] + bb1 + xa.y);
        *(float2*)(out + nb) = make_float2(o[idx][2] + bb0 + xb.x, o[idx][3] + bb1 + xb.y);
    }
}

// ===========================================================================
extern "C" void kernel_launch(void* const* d_in, const int* in_sizes, int n_in,
                              void* d_out, int out_size)
{
    const float* x    = (const float*)d_in[0];
    const float* ln1g = (const float*)d_in[1];
    const float* ln1b = (const float*)d_in[2];
    const float* Wp   = (const float*)d_in[3];
    const float* bp   = (const float*)d_in[4];
    const float* ln2g = (const float*)d_in[5];
    const float* ln2b = (const float*)d_in[6];
    const float* W1   = (const float*)d_in[7];
    const float* b1   = (const float*)d_in[8];
    const float* W2   = (const float*)d_in[9];
    const float* b2   = (const float*)d_in[10];
    float* out = (float*)d_out;

    const int smem1 = (64 * 192 + 64 * 65) * 4;

    cudaFuncSetAttribute(k1_ln_qkv,   cudaFuncAttributeMaxDynamicSharedMemorySize, smem1);
    cudaFuncSetAttribute(k2_attn_mma, cudaFuncAttributeMaxDynamicSharedMemorySize, SM2_TOTAL);
    cudaFuncSetAttribute(k3a_ln_fc1,  cudaFuncAttributeMaxDynamicSharedMemorySize, K3A_TOTAL);
    cudaFuncSetAttribute(k3b_fc2,     cudaFuncAttributeMaxDynamicSharedMemorySize, K3B_TOTAL);

    kprep<<<64, 256>>>(W1, W2);
    k1_ln_qkv<<<NTOK / 64, 256, smem1>>>(x, ln1g, ln1b, Wp, bp);
    k2_attn_mma<<<dim3(SS / 128, BB * HH), 256, SM2_TOTAL>>>();
    k3a_ln_fc1<<<NTOK / 128, 512, K3A_TOTAL>>>(ln2g, ln2b, b1);
    k3b_fc2<<<NTOK / 128, 256, K3B_TOTAL>>>(x, b2, out);
}

// round 6
// speedup vs baseline: 8.9535x; 1.1022x over previous
#include <cuda_runtime.h>
#include <cuda_bf16.h>
#include <cuda_fp16.h>
#include <math.h>
#include <stdint.h>

#define BB 4
#define SS 2048
#define HH 8
#define DD 64
#define NTOK (BB*SS*HH)   // 65536 tokens

// Scratch (allocation-free rule: __device__ globals)
__device__ __nv_bfloat16 g_qkh[(size_t)NTOK * 128];  // [n][128] q|k hi parts
__device__ __nv_bfloat16 g_qkl[(size_t)NTOK * 128];  // [n][128] q|k lo parts
__device__ __half        g_v  [(size_t)NTOK * 64];   // [n][64]  v fp16
__device__ float         g_attn[(size_t)NTOK * 64];  // [n][64]  attention out
__device__ __half        g_h1 [(size_t)NTOK * 256];  // [n][256] gelu(h1) fp16
// Pre-transposed / split weights
__device__ __nv_bfloat16 g_wph[192 * 64];            // Wp^T [n][k] hi
__device__ __nv_bfloat16 g_wpl[192 * 64];            // Wp^T [n][k] lo
__device__ __nv_bfloat16 g_w1h[256 * 64];            // W1^T [n][k] hi
__device__ __nv_bfloat16 g_w1l[256 * 64];            // W1^T [n][k] lo
__device__ __half        g_w2h[64 * 256];            // W2^T [n][k] hi (fp16)
__device__ __half        g_w2l[64 * 256];            // W2^T [n][k] lo (fp16)

// ===========================================================================
// helpers
// ===========================================================================
__device__ __forceinline__ uint32_t smem_u32(const void* p) {
    uint32_t a;
    asm("{ .reg .u64 t; cvta.to.shared.u64 t, %1; cvt.u32.u64 %0, t; }"
        : "=r"(a) : "l"(p));
    return a;
}
__device__ __forceinline__ uint32_t packh2(float a, float b) {
    __half2 h = __floats2half2_rn(a, b);
    return *reinterpret_cast<uint32_t*>(&h);
}
__device__ __forceinline__ uint32_t packbf2(float a, float b) {
    __nv_bfloat16 ha = __float2bfloat16(a), hb = __float2bfloat16(b);
    return (uint32_t)__bfloat16_as_ushort(ha) | ((uint32_t)__bfloat16_as_ushort(hb) << 16);
}
__device__ __forceinline__ void split2bf(float a, float b, uint32_t& hi, uint32_t& lo) {
    __nv_bfloat16 ha = __float2bfloat16(a), hb = __float2bfloat16(b);
    hi = (uint32_t)__bfloat16_as_ushort(ha) | ((uint32_t)__bfloat16_as_ushort(hb) << 16);
    lo = packbf2(a - __bfloat162float(ha), b - __bfloat162float(hb));
}

#define LDSM_X4(r0,r1,r2,r3, addr) \
    asm volatile("ldmatrix.sync.aligned.m8n8.x4.shared.b16 {%0,%1,%2,%3}, [%4];" \
        : "=r"(r0), "=r"(r1), "=r"(r2), "=r"(r3) : "r"(addr))
#define LDSM_X4_T(r0,r1,r2,r3, addr) \
    asm volatile("ldmatrix.sync.aligned.m8n8.x4.trans.shared.b16 {%0,%1,%2,%3}, [%4];" \
        : "=r"(r0), "=r"(r1), "=r"(r2), "=r"(r3) : "r"(addr))

__device__ __forceinline__ void mma_bf(float* d, uint32_t a0, uint32_t a1,
                                       uint32_t a2, uint32_t a3,
                                       uint32_t b0, uint32_t b1) {
    asm volatile(
        "mma.sync.aligned.m16n8k16.row.col.f32.bf16.bf16.f32 "
        "{%0,%1,%2,%3}, {%4,%5,%6,%7}, {%8,%9}, {%0,%1,%2,%3};"
        : "+f"(d[0]), "+f"(d[1]), "+f"(d[2]), "+f"(d[3])
        : "r"(a0), "r"(a1), "r"(a2), "r"(a3), "r"(b0), "r"(b1));
}
__device__ __forceinline__ void mma_fp(float* d, uint32_t a0, uint32_t a1,
                                       uint32_t a2, uint32_t a3,
                                       uint32_t b0, uint32_t b1) {
    asm volatile(
        "mma.sync.aligned.m16n8k16.row.col.f32.f16.f16.f32 "
        "{%0,%1,%2,%3}, {%4,%5,%6,%7}, {%8,%9}, {%0,%1,%2,%3};"
        : "+f"(d[0]), "+f"(d[1]), "+f"(d[2]), "+f"(d[3])
        : "r"(a0), "r"(a1), "r"(a2), "r"(a3), "r"(b0), "r"(b1));
}

#define CPA(dst, src) asm volatile("cp.async.cg.shared.global [%0], [%1], 16;" \
        :: "r"(dst), "l"(src) : "memory")
#define CPC() asm volatile("cp.async.commit_group;" ::: "memory")
#define CPW(n) asm volatile("cp.async.wait_group %0;" :: "n"(n) : "memory")

// ===========================================================================
// Kernel 0: weight prep (transpose + split).  64 blocks x 256 threads.
// ===========================================================================
__global__ __launch_bounds__(256)
void kprep(const float* __restrict__ Wp, const float* __restrict__ W1,
           const float* __restrict__ W2)
{
    const int i = blockIdx.x * 256 + threadIdx.x;   // 0..16383
    if (i < 12288) {
        const int k = i / 192, n = i % 192;         // Wp [64][192]
        const float v = Wp[k * 192 + n];
        __nv_bfloat16 hv = __float2bfloat16(v);
        g_wph[n * 64 + k] = hv;
        g_wpl[n * 64 + k] = __float2bfloat16(v - __bfloat162float(hv));
    }
    {
        const int k = i >> 8, n = i & 255;          // W1 [64][256]
        const float v = W1[k * 256 + n];
        __nv_bfloat16 hv = __float2bfloat16(v);
        g_w1h[n * 64 + k] = hv;
        g_w1l[n * 64 + k] = __float2bfloat16(v - __bfloat162float(hv));
    }
    {
        const int k = i >> 6, n = i & 63;           // W2 [256][64]
        const float v = W2[k * 64 + n];
        __half hv = __float2half(v);
        g_w2h[n * 256 + k] = hv;
        g_w2l[n * 256 + k] = __float2half(v - __half2float(hv));
    }
}

// ===========================================================================
// Kernel 1: LN1 + QKV projection via HMMA (bf16 3-term).
// 256 threads (8 warps), 64 tokens/block.  grid = NTOK/64.
// smem: sA [64][272] @0 ; sWp [192][272] @17408.  total 69632.
// warps: tg=(wid&3)*16 tokens, n0=(wid>>2)*96 cols.
// ===========================================================================
#define K1_SW 17408
#define K1_TOTAL (K1_SW + 192 * 272)    // 69632

__global__ __launch_bounds__(256)
void k1_ln_qkv(const float* __restrict__ x,
               const float* __restrict__ g1, const float* __restrict__ b1v,
               const float* __restrict__ bp)
{
    extern __shared__ char smc[];
    const uint32_t sb = smem_u32(smc);
    const int tid = threadIdx.x;
    const int t0 = blockIdx.x * 64;

    // async-load WpT hi/lo: 192 rows x 16 chunks
    for (int it = tid; it < 3072; it += 256) {
        const int n = it >> 4, c = it & 15;
        const char* src = (c < 8)
            ? (const char*)(g_wph + n * 64 + c * 8)
            : (const char*)(g_wpl + n * 64 + (c - 8) * 8);
        CPA(sb + K1_SW + n * 272 + c * 16, src);
    }
    CPC();

    // LN1: 4 threads/token, 16 elems each; split hi/lo into sA
    {
        const int tt = tid >> 2, sub = tid & 3;
        const size_t base = ((size_t)(t0 + tt)) * 64 + sub * 16;
        float v[16];
        const float4* xp = (const float4*)(x + base);
        #pragma unroll
        for (int q = 0; q < 4; q++) {
            float4 f = xp[q];
            v[4*q+0] = f.x; v[4*q+1] = f.y; v[4*q+2] = f.z; v[4*q+3] = f.w;
        }
        float s = 0.f;
        #pragma unroll
        for (int q = 0; q < 16; q++) s += v[q];
        s += __shfl_xor_sync(0xffffffffu, s, 1);
        s += __shfl_xor_sync(0xffffffffu, s, 2);
        const float mean = s * (1.f / 64.f);
        float vs = 0.f;
        #pragma unroll
        for (int q = 0; q < 16; q++) { float d = v[q] - mean; vs += d * d; }
        vs += __shfl_xor_sync(0xffffffffu, vs, 1);
        vs += __shfl_xor_sync(0xffffffffu, vs, 2);
        const float rs = rsqrtf(vs * (1.f / 64.f) + 1e-5f);
        float r[16];
        #pragma unroll
        for (int q = 0; q < 16; q++) {
            const int d = sub * 16 + q;
            r[q] = (v[q] - mean) * rs * g1[d] + b1v[d];
        }
        uint32_t hw[8], lw[8];
        #pragma unroll
        for (int q = 0; q < 8; q++) split2bf(r[2*q], r[2*q+1], hw[q], lw[q]);
        char* dst = smc + (tt * 272 + sub * 32);
        *(uint4*)(dst)            = make_uint4(hw[0], hw[1], hw[2], hw[3]);
        *(uint4*)(dst + 16)       = make_uint4(hw[4], hw[5], hw[6], hw[7]);
        *(uint4*)(dst + 128)      = make_uint4(lw[0], lw[1], lw[2], lw[3]);
        *(uint4*)(dst + 128 + 16) = make_uint4(lw[4], lw[5], lw[6], lw[7]);
    }
    CPW(0);
    __syncthreads();

    const int wid = tid >> 5, lane = tid & 31;
    const int g = lane >> 3, lr = lane & 7;
    const int tg = (wid & 3) * 16;
    const int n0 = (wid >> 2) * 96;

    const uint32_t aA = sb + (uint32_t)(tg + (g & 1) * 8 + lr) * 272 + (g >> 1) * 16;
    const uint32_t bW = sb + K1_SW + (uint32_t)(n0 + (g >> 1) * 8 + lr) * 272 + (g & 1) * 16;

    float s[12][4];
    #pragma unroll
    for (int j = 0; j < 12; j++)
        #pragma unroll
        for (int e = 0; e < 4; e++) s[j][e] = 0.f;

    #pragma unroll
    for (int ks = 0; ks < 4; ks++) {
        uint32_t ah0, ah1, ah2, ah3, al0, al1, al2, al3;
        LDSM_X4(ah0, ah1, ah2, ah3, aA + ks * 32);
        LDSM_X4(al0, al1, al2, al3, aA + 128 + ks * 32);
        #pragma unroll
        for (int j = 0; j < 6; j++) {
            uint32_t wh0, wh1, wh2, wh3, wl0, wl1, wl2, wl3;
            LDSM_X4(wh0, wh1, wh2, wh3, bW + j * (16 * 272) + ks * 32);
            LDSM_X4(wl0, wl1, wl2, wl3, bW + j * (16 * 272) + 128 + ks * 32);
            mma_bf(s[2*j],     ah0, ah1, ah2, ah3, wh0, wh1);
            mma_bf(s[2*j + 1], ah0, ah1, ah2, ah3, wh2, wh3);
            mma_bf(s[2*j],     al0, al1, al2, al3, wh0, wh1);
            mma_bf(s[2*j + 1], al0, al1, al2, al3, wh2, wh3);
            mma_bf(s[2*j],     ah0, ah1, ah2, ah3, wl0, wl1);
            mma_bf(s[2*j + 1], ah0, ah1, ah2, ah3, wl2, wl3);
        }
    }

    // epilogue: +bp; q/k -> split bf16 hi/lo, v -> fp16
    const int r0 = t0 + tg + (lane >> 2);
    const int c0 = 2 * (lane & 3);
    #pragma unroll
    for (int idx = 0; idx < 12; idx++) {
        const int col = n0 + (idx >> 1) * 16 + (idx & 1) * 8 + c0;
        const float bb0 = bp[col], bb1 = bp[col + 1];
        const float v0 = s[idx][0] + bb0, v1 = s[idx][1] + bb1;
        const float v2 = s[idx][2] + bb0, v3 = s[idx][3] + bb1;
        if (col < 128) {
            uint32_t h01, l01, h23, l23;
            split2bf(v0, v1, h01, l01);
            split2bf(v2, v3, h23, l23);
            *(uint32_t*)(g_qkh + (size_t)r0 * 128 + col)       = h01;
            *(uint32_t*)(g_qkl + (size_t)r0 * 128 + col)       = l01;
            *(uint32_t*)(g_qkh + (size_t)(r0 + 8) * 128 + col) = h23;
            *(uint32_t*)(g_qkl + (size_t)(r0 + 8) * 128 + col) = l23;
        } else {
            *(uint32_t*)(g_v + (size_t)r0 * 64 + col - 128)       = packh2(v0, v1);
            *(uint32_t*)(g_v + (size_t)(r0 + 8) * 64 + col - 128) = packh2(v2, v3);
        }
    }
}

// smem byte layout for k2
#define QPITCH 272
#define KPITCH 272
#define VPITCH 144
#define SM_Q   0
#define SM_KB  (128 * QPITCH)
#define KBUF   (64 * KPITCH)
#define SM_VB  (SM_KB + 2 * KBUF)
#define VBUF   (64 * VPITCH)
#define SM2_TOTAL (SM_VB + 2 * VBUF)        // 88064

// ===========================================================================
// Kernel 2: flash attention.  QK: bf16 3-term hi/lo.  PV: fp16 1-term.
// (unchanged from R4/R5)
// ===========================================================================
__global__ __launch_bounds__(256, 2)
void k2_attn_mma()
{
    extern __shared__ char smc[];
    const uint32_t sb = smem_u32(smc);

    const int tid  = threadIdx.x;
    const int wid  = tid >> 5;
    const int lane = tid & 31;
    const int b = blockIdx.y >> 3, h = blockIdx.y & 7;
    const int q0 = blockIdx.x * 128;
    const int m0 = wid * 16;

    const int g  = lane >> 3;
    const int lr = lane & 7;

    const uint32_t aQ   = sb + SM_Q + (uint32_t)(m0 + (g & 1) * 8 + lr) * QPITCH + (g >> 1) * 16;
    const uint32_t kOff = (uint32_t)((g >> 1) * 8 + lr) * KPITCH + (g & 1) * 16;
    const uint32_t vOff = (uint32_t)((g & 1) * 8 + lr) * VPITCH + (g >> 1) * 16;

    {
        for (int it = tid; it < 2048; it += 256) {
            const int row = it >> 4, c = it & 15;
            const size_t n = ((size_t)(b * SS + q0 + row)) * HH + h;
            const char* src = (c < 8)
                ? (const char*)(g_qkh + n * 128 + c * 8)
                : (const char*)(g_qkl + n * 128 + (c - 8) * 8);
            CPA(sb + SM_Q + row * QPITCH + c * 16, src);
        }
        for (int it = tid; it < 1024; it += 256) {
            const int row = it >> 4, c = it & 15;
            const size_t n = ((size_t)(b * SS + row)) * HH + h;
            const char* src = (c < 8)
                ? (const char*)(g_qkh + n * 128 + 64 + c * 8)
                : (const char*)(g_qkl + n * 128 + 64 + (c - 8) * 8);
            CPA(sb + SM_KB + row * KPITCH + c * 16, src);
        }
        for (int it = tid; it < 512; it += 256) {
            const int row = it >> 3, c = it & 7;
            const size_t n = ((size_t)(b * SS + row)) * HH + h;
            CPA(sb + SM_VB + row * VPITCH + c * 16, (const char*)(g_v + n * 64 + c * 8));
        }
        CPC();
    }

    float o[8][4];
    #pragma unroll
    for (int j = 0; j < 8; j++)
        #pragma unroll
        for (int e = 0; e < 4; e++) o[j][e] = 0.f;
    float mrow0 = -INFINITY, mrow1 = -INFINITY;
    float lsum0 = 0.f, lsum1 = 0.f;

    for (int kt = 0; kt < SS / 64; kt++) {
        __syncthreads();
        if (kt + 1 < SS / 64) {
            const int k0n = (kt + 1) * 64;
            const uint32_t dK = sb + SM_KB + ((kt + 1) & 1) * KBUF;
            const uint32_t dV = sb + SM_VB + ((kt + 1) & 1) * VBUF;
            for (int it = tid; it < 1024; it += 256) {
                const int row = it >> 4, c = it & 15;
                const size_t n = ((size_t)(b * SS + k0n + row)) * HH + h;
                const char* src = (c < 8)
                    ? (const char*)(g_qkh + n * 128 + 64 + c * 8)
                    : (const char*)(g_qkl + n * 128 + 64 + (c - 8) * 8);
                CPA(dK + row * KPITCH + c * 16, src);
            }
            for (int it = tid; it < 512; it += 256) {
                const int row = it >> 3, c = it & 7;
                const size_t n = ((size_t)(b * SS + k0n + row)) * HH + h;
                CPA(dV + row * VPITCH + c * 16, (const char*)(g_v + n * 64 + c * 8));
            }
            CPC();
            CPW(1);
        } else {
            CPW(0);
        }
        __syncthreads();

        const uint32_t bK = sb + SM_KB + (kt & 1) * KBUF + kOff;
        const uint32_t bV = sb + SM_VB + (kt & 1) * VBUF + vOff;

        float s[8][4];
        #pragma unroll
        for (int j = 0; j < 8; j++)
            #pragma unroll
            for (int e = 0; e < 4; e++) s[j][e] = 0.f;

        #pragma unroll
        for (int ks = 0; ks < 4; ks++) {
            uint32_t qh0, qh1, qh2, qh3, ql0, ql1, ql2, ql3;
            LDSM_X4(qh0, qh1, qh2, qh3, aQ + ks * 32);
            LDSM_X4(ql0, ql1, ql2, ql3, aQ + 128 + ks * 32);
            #pragma unroll
            for (int j = 0; j < 4; j++) {
                uint32_t kh0, kh1, kh2, kh3, kl0, kl1, kl2, kl3;
                LDSM_X4(kh0, kh1, kh2, kh3, bK + j * (16 * KPITCH) + ks * 32);
                LDSM_X4(kl0, kl1, kl2, kl3, bK + j * (16 * KPITCH) + 128 + ks * 32);
                mma_bf(s[2*j],     qh0, qh1, qh2, qh3, kh0, kh1);
                mma_bf(s[2*j + 1], qh0, qh1, qh2, qh3, kh2, kh3);
                mma_bf(s[2*j],     ql0, ql1, ql2, ql3, kh0, kh1);
                mma_bf(s[2*j + 1], ql0, ql1, ql2, ql3, kh2, kh3);
                mma_bf(s[2*j],     qh0, qh1, qh2, qh3, kl0, kl1);
                mma_bf(s[2*j + 1], qh0, qh1, qh2, qh3, kl2, kl3);
            }
        }

        float t0 = -INFINITY, t1 = -INFINITY;
        #pragma unroll
        for (int j = 0; j < 8; j++) {
            t0 = fmaxf(t0, fmaxf(s[j][0], s[j][1]));
            t1 = fmaxf(t1, fmaxf(s[j][2], s[j][3]));
        }
        t0 = fmaxf(t0, __shfl_xor_sync(0xffffffffu, t0, 1));
        t0 = fmaxf(t0, __shfl_xor_sync(0xffffffffu, t0, 2));
        t1 = fmaxf(t1, __shfl_xor_sync(0xffffffffu, t1, 1));
        t1 = fmaxf(t1, __shfl_xor_sync(0xffffffffu, t1, 2));
        const float mn0 = fmaxf(mrow0, t0);
        const float mn1 = fmaxf(mrow1, t1);
        const float sc0 = __expf(mrow0 - mn0);
        const float sc1 = __expf(mrow1 - mn1);
        mrow0 = mn0; mrow1 = mn1;

        float acc0 = 0.f, acc1 = 0.f;
        #pragma unroll
        for (int j = 0; j < 8; j++) {
            s[j][0] = __expf(s[j][0] - mn0);
            s[j][1] = __expf(s[j][1] - mn0);
            s[j][2] = __expf(s[j][2] - mn1);
            s[j][3] = __expf(s[j][3] - mn1);
            acc0 += s[j][0] + s[j][1];
            acc1 += s[j][2] + s[j][3];
        }
        lsum0 = lsum0 * sc0 + acc0;
        lsum1 = lsum1 * sc1 + acc1;
        #pragma unroll
        for (int j = 0; j < 8; j++) {
            o[j][0] *= sc0; o[j][1] *= sc0;
            o[j][2] *= sc1; o[j][3] *= sc1;
        }

        #pragma unroll
        for (int kk = 0; kk < 4; kk++) {
            const uint32_t p0 = packh2(s[2*kk][0],     s[2*kk][1]);
            const uint32_t p1 = packh2(s[2*kk][2],     s[2*kk][3]);
            const uint32_t p2 = packh2(s[2*kk + 1][0], s[2*kk + 1][1]);
            const uint32_t p3 = packh2(s[2*kk + 1][2], s[2*kk + 1][3]);
            #pragma unroll
            for (int j = 0; j < 4; j++) {
                uint32_t v0, v1, v2, v3;
                LDSM_X4_T(v0, v1, v2, v3, bV + kk * (16 * VPITCH) + j * 32);
                mma_fp(o[2*j],     p0, p1, p2, p3, v0, v1);
                mma_fp(o[2*j + 1], p0, p1, p2, p3, v2, v3);
            }
        }
    }

    lsum0 += __shfl_xor_sync(0xffffffffu, lsum0, 1);
    lsum0 += __shfl_xor_sync(0xffffffffu, lsum0, 2);
    lsum1 += __shfl_xor_sync(0xffffffffu, lsum1, 1);
    lsum1 += __shfl_xor_sync(0xffffffffu, lsum1, 2);
    const float inv0 = 1.f / lsum0, inv1 = 1.f / lsum1;

    const int r0 = q0 + m0 + (lane >> 2);
    const int c0 = (lane & 3) * 2;
    const size_t n0 = ((size_t)(b * SS + r0)) * HH + h;
    const size_t n1 = ((size_t)(b * SS + r0 + 8)) * HH + h;
    #pragma unroll
    for (int j = 0; j < 8; j++) {
        float2 v0 = make_float2(o[j][0] * inv0, o[j][1] * inv0);
        float2 v1 = make_float2(o[j][2] * inv1, o[j][3] * inv1);
        *(float2*)(g_attn + n0 * 64 + 8 * j + c0) = v0;
        *(float2*)(g_attn + n1 * 64 + 8 * j + c0) = v1;
    }
}

// ===========================================================================
// Kernel 3a: LN2 + GEMM1 (bf16 3-term) + exact gelu -> g_h1 (fp16).
// 256 threads (8 warps), 64 tokens/block.  grid = NTOK/64.  2 CTAs/SM.
// smem: sA [64][272] @0 ; sW1 [256][272] @17408.  total 87040.
// ===========================================================================
#define K3A_SW1 17408
#define K3A_TOTAL (K3A_SW1 + 256 * 272)   // 87040

__global__ __launch_bounds__(256)
void k3a_ln_fc1(const float* __restrict__ g2, const float* __restrict__ b2v,
                const float* __restrict__ b1m)
{
    extern __shared__ char smc[];
    const uint32_t sb = smem_u32(smc);
    const int tid = threadIdx.x;
    const int t0 = blockIdx.x * 64;

    // async-load W1T hi/lo: 256 rows x 16 chunks
    for (int it = tid; it < 4096; it += 256) {
        const int n = it >> 4, c = it & 15;
        const char* src = (c < 8)
            ? (const char*)(g_w1h + n * 64 + c * 8)
            : (const char*)(g_w1l + n * 64 + (c - 8) * 8);
        CPA(sb + K3A_SW1 + n * 272 + c * 16, src);
    }
    CPC();

    // LN2: 4 threads/token, 16 elems each; split hi/lo into sA
    {
        const int tt = tid >> 2, sub = tid & 3;
        const size_t base = ((size_t)(t0 + tt)) * 64 + sub * 16;
        float v[16];
        const float4* ap = (const float4*)(g_attn + base);
        #pragma unroll
        for (int q = 0; q < 4; q++) {
            float4 f = ap[q];
            v[4*q+0] = f.x; v[4*q+1] = f.y; v[4*q+2] = f.z; v[4*q+3] = f.w;
        }
        float s = 0.f;
        #pragma unroll
        for (int q = 0; q < 16; q++) s += v[q];
        s += __shfl_xor_sync(0xffffffffu, s, 1);
        s += __shfl_xor_sync(0xffffffffu, s, 2);
        const float mean = s * (1.f / 64.f);
        float vs = 0.f;
        #pragma unroll
        for (int q = 0; q < 16; q++) { float d = v[q] - mean; vs += d * d; }
        vs += __shfl_xor_sync(0xffffffffu, vs, 1);
        vs += __shfl_xor_sync(0xffffffffu, vs, 2);
        const float rs = rsqrtf(vs * (1.f / 64.f) + 1e-5f);
        float r[16];
        #pragma unroll
        for (int q = 0; q < 16; q++) {
            const int d = sub * 16 + q;
            r[q] = (v[q] - mean) * rs * g2[d] + b2v[d];
        }
        uint32_t hw[8], lw[8];
        #pragma unroll
        for (int q = 0; q < 8; q++) split2bf(r[2*q], r[2*q+1], hw[q], lw[q]);
        char* dst = smc + (tt * 272 + sub * 32);
        *(uint4*)(dst)            = make_uint4(hw[0], hw[1], hw[2], hw[3]);
        *(uint4*)(dst + 16)       = make_uint4(hw[4], hw[5], hw[6], hw[7]);
        *(uint4*)(dst + 128)      = make_uint4(lw[0], lw[1], lw[2], lw[3]);
        *(uint4*)(dst + 128 + 16) = make_uint4(lw[4], lw[5], lw[6], lw[7]);
    }
    CPW(0);
    __syncthreads();

    // GEMM1: warp w: tokens (w&3)*16.., cols (w>>2)*128..
    const int wid = tid >> 5, lane = tid & 31;
    const int g = lane >> 3, lr = lane & 7;
    const int tg = (wid & 3) * 16;
    const int n0 = (wid >> 2) * 128;

    const uint32_t aA = sb + (uint32_t)(tg + (g & 1) * 8 + lr) * 272 + (g >> 1) * 16;
    const uint32_t bW = sb + K3A_SW1 + (uint32_t)(n0 + (g >> 1) * 8 + lr) * 272 + (g & 1) * 16;

    float s[16][4];
    #pragma unroll
    for (int j = 0; j < 16; j++)
        #pragma unroll
        for (int e = 0; e < 4; e++) s[j][e] = 0.f;

    #pragma unroll
    for (int ks = 0; ks < 4; ks++) {
        uint32_t ah0, ah1, ah2, ah3, al0, al1, al2, al3;
        LDSM_X4(ah0, ah1, ah2, ah3, aA + ks * 32);
        LDSM_X4(al0, al1, al2, al3, aA + 128 + ks * 32);
        #pragma unroll
        for (int j = 0; j < 8; j++) {
            uint32_t wh0, wh1, wh2, wh3, wl0, wl1, wl2, wl3;
            LDSM_X4(wh0, wh1, wh2, wh3, bW + j * (16 * 272) + ks * 32);
            LDSM_X4(wl0, wl1, wl2, wl3, bW + j * (16 * 272) + 128 + ks * 32);
            mma_bf(s[2*j],     ah0, ah1, ah2, ah3, wh0, wh1);
            mma_bf(s[2*j + 1], ah0, ah1, ah2, ah3, wh2, wh3);
            mma_bf(s[2*j],     al0, al1, al2, al3, wh0, wh1);
            mma_bf(s[2*j + 1], al0, al1, al2, al3, wh2, wh3);
            mma_bf(s[2*j],     ah0, ah1, ah2, ah3, wl0, wl1);
            mma_bf(s[2*j + 1], ah0, ah1, ah2, ah3, wl2, wl3);
        }
    }

    // epilogue: +b1, exact gelu, fp16 store
    const int r0 = t0 + tg + (lane >> 2);
    const int c0 = 2 * (lane & 3);
    #pragma unroll
    for (int idx = 0; idx < 16; idx++) {
        const int col = n0 + (idx >> 1) * 16 + (idx & 1) * 8 + c0;
        const float bb0 = b1m[col], bb1 = b1m[col + 1];
        float z0 = s[idx][0] + bb0, z1 = s[idx][1] + bb1;
        float z2 = s[idx][2] + bb0, z3 = s[idx][3] + bb1;
        z0 = 0.5f * z0 * (1.f + erff(z0 * 0.70710678118654752f));
        z1 = 0.5f * z1 * (1.f + erff(z1 * 0.70710678118654752f));
        z2 = 0.5f * z2 * (1.f + erff(z2 * 0.70710678118654752f));
        z3 = 0.5f * z3 * (1.f + erff(z3 * 0.70710678118654752f));
        *(uint32_t*)(g_h1 + (size_t)r0 * 256 + col)       = packh2(z0, z1);
        *(uint32_t*)(g_h1 + (size_t)(r0 + 8) * 256 + col) = packh2(z2, z3);
    }
}

// ===========================================================================
// Kernel 3b: GEMM2 (fp16 2-term) + bias + residual -> out.
// 256 threads (8 warps), 64 tokens/block.  grid = NTOK/64.  2 CTAs/SM.
// smem: sH [64][528] @0 ; sW2 [64][1040] @33792.  total 100352.
// warps: tg=(wid&3)*16 tokens, n0=(wid>>2)*32 cols.
// ===========================================================================
#define K3B_SW2 33792
#define K3B_TOTAL (K3B_SW2 + 64 * 1040)   // 100352

__global__ __launch_bounds__(256)
void k3b_fc2(const float* __restrict__ x, const float* __restrict__ b2m,
             float* __restrict__ out)
{
    extern __shared__ char smc[];
    const uint32_t sb = smem_u32(smc);
    const int tid = threadIdx.x;
    const int t0 = blockIdx.x * 64;

    // async-load W2T hi/lo fp16: 64 rows x 64 chunks
    for (int it = tid; it < 4096; it += 256) {
        const int n = it >> 6, c = it & 63;
        const char* src = (c < 32)
            ? (const char*)(g_w2h + n * 256 + c * 8)
            : (const char*)(g_w2l + n * 256 + (c - 32) * 8);
        CPA(sb + K3B_SW2 + n * 1040 + ((c < 32) ? c * 16 : 512 + (c - 32) * 16), src);
    }
    // async-load H tile: 64 rows x 32 chunks
    for (int it = tid; it < 2048; it += 256) {
        const int row = it >> 5, c = it & 31;
        CPA(sb + row * 528 + c * 16,
            (const char*)(g_h1 + (size_t)(t0 + row) * 256 + c * 8));
    }
    CPC();
    CPW(0);
    __syncthreads();

    const int wid = tid >> 5, lane = tid & 31;
    const int g = lane >> 3, lr = lane & 7;
    const int tg = (wid & 3) * 16;
    const int n0 = (wid >> 2) * 32;

    const uint32_t aH = sb + (uint32_t)(tg + (g & 1) * 8 + lr) * 528 + (g >> 1) * 16;
    const uint32_t bW = sb + K3B_SW2 + (uint32_t)(n0 + (g >> 1) * 8 + lr) * 1040 + (g & 1) * 16;

    float o[4][4];
    #pragma unroll
    for (int j = 0; j < 4; j++)
        #pragma unroll
        for (int e = 0; e < 4; e++) o[j][e] = 0.f;

    #pragma unroll
    for (int ks = 0; ks < 16; ks++) {
        uint32_t ah0, ah1, ah2, ah3;
        LDSM_X4(ah0, ah1, ah2, ah3, aH + ks * 32);
        #pragma unroll
        for (int j = 0; j < 2; j++) {
            uint32_t wh0, wh1, wh2, wh3, wl0, wl1, wl2, wl3;
            LDSM_X4(wh0, wh1, wh2, wh3, bW + j * (16 * 1040) + ks * 32);
            LDSM_X4(wl0, wl1, wl2, wl3, bW + j * (16 * 1040) + 512 + ks * 32);
            mma_fp(o[2*j],     ah0, ah1, ah2, ah3, wh0, wh1);
            mma_fp(o[2*j + 1], ah0, ah1, ah2, ah3, wh2, wh3);
            mma_fp(o[2*j],     ah0, ah1, ah2, ah3, wl0, wl1);
            mma_fp(o[2*j + 1], ah0, ah1, ah2, ah3, wl2, wl3);
        }
    }

    // epilogue: + b2 + residual x
    const int r0 = t0 + tg + (lane >> 2);
    const int c0 = 2 * (lane & 3);
    #pragma unroll
    for (int idx = 0; idx < 4; idx++) {
        const int col = n0 + (idx >> 1) * 16 + (idx & 1) * 8 + c0;
        const float bb0 = b2m[col], bb1 = b2m[col + 1];
        const size_t na = (size_t)r0 * 64 + col;
        const size_t nb = (size_t)(r0 + 8) * 64 + col;
        float2 xa = *(const float2*)(x + na);
        float2 xb = *(const float2*)(x + nb);
        *(float2*)(out + na) = make_float2(o[idx][0] + bb0 + xa.x, o[idx][1] + bb1 + xa.y);
        *(float2*)(out + nb) = make_float2(o[idx][2] + bb0 + xb.x, o[idx][3] + bb1 + xb.y);
    }
}

// ===========================================================================
extern "C" void kernel_launch(void* const* d_in, const int* in_sizes, int n_in,
                              void* d_out, int out_size)
{
    const float* x    = (const float*)d_in[0];
    const float* ln1g = (const float*)d_in[1];
    const float* ln1b = (const float*)d_in[2];
    const float* Wp   = (const float*)d_in[3];
    const float* bp   = (const float*)d_in[4];
    const float* ln2g = (const float*)d_in[5];
    const float* ln2b = (const float*)d_in[6];
    const float* W1   = (const float*)d_in[7];
    const float* b1   = (const float*)d_in[8];
    const float* W2   = (const float*)d_in[9];
    const float* b2   = (const float*)d_in[10];
    float* out = (float*)d_out;

    cudaFuncSetAttribute(k1_ln_qkv,   cudaFuncAttributeMaxDynamicSharedMemorySize, K1_TOTAL);
    cudaFuncSetAttribute(k2_attn_mma, cudaFuncAttributeMaxDynamicSharedMemorySize, SM2_TOTAL);
    cudaFuncSetAttribute(k3a_ln_fc1,  cudaFuncAttributeMaxDynamicSharedMemorySize, K3A_TOTAL);
    cudaFuncSetAttribute(k3b_fc2,     cudaFuncAttributeMaxDynamicSharedMemorySize, K3B_TOTAL);

    kprep<<<64, 256>>>(Wp, W1, W2);
    k1_ln_qkv<<<NTOK / 64, 256, K1_TOTAL>>>(x, ln1g, ln1b, bp);
    k2_attn_mma<<<dim3(SS / 128, BB * HH), 256, SM2_TOTAL>>>();
    k3a_ln_fc1<<<NTOK / 64, 256, K3A_TOTAL>>>(ln2g, ln2b, b1);
    k3b_fc2<<<NTOK / 64, 256, K3B_TOTAL>>>(x, b2, out);
}